// round 14
// baseline (speedup 1.0000x reference)
#include <cuda_runtime.h>
#include <cuda_fp16.h>
#include <math.h>
#include <stdint.h>

// Problem constants
#define B_  8
#define N_  1024
#define C_  384
#define H_  12
#define HD_ 32
#define HID_ 768
#define M_  (B_ * N_)
#define NREL_ 3969
#define SCALE_ 0.17677669529663687f
#define LOG2E_ 1.4426950408889634f

// NOTE: harness PTX target is sm_103 (no 'a') -> tcgen05.* unavailable.

__device__ __forceinline__ float gelu_f(float v) {
    return 0.5f * v * (1.0f + erff(v * 0.70710678118654752f));
}

__device__ __forceinline__ void mma_f16(float* c, const uint32_t* a, const uint32_t* b) {
    asm volatile(
        "mma.sync.aligned.m16n8k16.row.col.f32.f16.f16.f32 "
        "{%0,%1,%2,%3}, {%4,%5,%6,%7}, {%8,%9}, {%0,%1,%2,%3};"
        : "+f"(c[0]), "+f"(c[1]), "+f"(c[2]), "+f"(c[3])
        : "r"(a[0]), "r"(a[1]), "r"(a[2]), "r"(a[3]), "r"(b[0]), "r"(b[1]));
}

__device__ __forceinline__ void ldsm_x4(uint32_t* r, const __half* p) {
    uint32_t addr = (uint32_t)__cvta_generic_to_shared(p);
    asm volatile("ldmatrix.sync.aligned.m8n8.x4.shared.b16 {%0,%1,%2,%3}, [%4];"
                 : "=r"(r[0]), "=r"(r[1]), "=r"(r[2]), "=r"(r[3]) : "r"(addr));
}

__device__ __forceinline__ void ldsm_x2_t(uint32_t& r0, uint32_t& r1, const __half* p) {
    uint32_t addr = (uint32_t)__cvta_generic_to_shared(p);
    asm volatile("ldmatrix.sync.aligned.m8n8.x2.trans.shared.b16 {%0,%1}, [%2];"
                 : "=r"(r0), "=r"(r1) : "r"(addr));
}

// ---------------- scratch ----------------
__device__ __align__(16) __half g_ln2[M_ * C_];
__device__ __align__(16) __half g_h1 [M_ * HID_];
__device__ __align__(16) __half g_h2 [M_ * HID_];
__device__ float g_x1 [M_ * C_];
__device__ __align__(16) __half g_ln1[M_ * C_];
__device__ __align__(16) __half g_qkvh[M_ * 3 * C_];
__device__ __align__(16) __half g_atth[M_ * C_];
__device__ __align__(16) __half g_biash[H_ * N_ * N_];
__device__ __align__(16) __half g_wh[1179648];
#define OFF_QKV  0
#define OFF_PW1  442368
#define OFF_PW2  737280
#define OFF_PROJ 1032192
#define Q_QKV  110592
#define Q_PW1  184320
#define Q_PW2  258048
#define Q_END  294912

// ---------------- merged weight fp32 -> fp16 ----------------
__global__ __launch_bounds__(256) void w2h_all_kernel(
    const float* __restrict__ s_qkv, const float* __restrict__ s_pw1,
    const float* __restrict__ s_pw2, const float* __restrict__ s_proj,
    __half* __restrict__ dst)
{
    const int i = blockIdx.x * 256 + threadIdx.x;
    if (i >= Q_END) return;
    const float* src; int local;
    if (i < Q_QKV)      { src = s_qkv;  local = i; }
    else if (i < Q_PW1) { src = s_pw1;  local = i - Q_QKV; }
    else if (i < Q_PW2) { src = s_pw2;  local = i - Q_PW1; }
    else                { src = s_proj; local = i - Q_PW2; }
    const float4 v = ((const float4*)src)[local];
    __half2 h0 = __floats2half2_rn(v.x, v.y);
    __half2 h1 = __floats2half2_rn(v.z, v.w);
    uint2 u; u.x = *(uint32_t*)&h0; u.y = *(uint32_t*)&h1;
    *(uint2*)(dst + (size_t)i * 4) = u;
}

// ---------------- LayerNorm: warp-per-row, shfl-only -------------------------
__global__ __launch_bounds__(256) void ln_kernel(
    const float* __restrict__ in, const float* __restrict__ g,
    const float* __restrict__ bta, __half* __restrict__ out)
{
    const int lane = threadIdx.x & 31;
    const int row  = blockIdx.x * 8 + (threadIdx.x >> 5);
    const float4* xr = (const float4*)(in + (size_t)row * C_);
    const float4 a = xr[lane], b = xr[lane + 32], c = xr[lane + 64];

    float s = (a.x + a.y) + (a.z + a.w) + (b.x + b.y) + (b.z + b.w)
            + (c.x + c.y) + (c.z + c.w);
    #pragma unroll
    for (int o = 16; o; o >>= 1) s += __shfl_xor_sync(0xffffffffu, s, o);
    const float mean = s * (1.0f / C_);

    const float dx[12] = { a.x - mean, a.y - mean, a.z - mean, a.w - mean,
                           b.x - mean, b.y - mean, b.z - mean, b.w - mean,
                           c.x - mean, c.y - mean, c.z - mean, c.w - mean };
    float q = 0.0f;
    #pragma unroll
    for (int i = 0; i < 12; i++) q += dx[i] * dx[i];
    #pragma unroll
    for (int o = 16; o; o >>= 1) q += __shfl_xor_sync(0xffffffffu, q, o);
    const float inv = rsqrtf(q * (1.0f / C_) + 1e-5f);

    const float4* g4 = (const float4*)g;
    const float4* t4 = (const float4*)bta;
    __half* orow = out + (size_t)row * C_;
    #pragma unroll
    for (int seg = 0; seg < 3; seg++) {
        const float4 gv = g4[lane + seg * 32];
        const float4 tv = t4[lane + seg * 32];
        const float* d = &dx[seg * 4];
        __half2 h0 = __floats2half2_rn(d[0] * inv * gv.x + tv.x,
                                       d[1] * inv * gv.y + tv.y);
        __half2 h1 = __floats2half2_rn(d[2] * inv * gv.z + tv.z,
                                       d[3] * inv * gv.w + tv.w);
        uint2 u; u.x = *(uint32_t*)&h0; u.y = *(uint32_t*)&h1;
        *(uint2*)(orow + lane * 4 + seg * 128) = u;
    }
}

// ---------------- fp16 GEMM: 4-stage cp.async, 1 barrier/iter ---------------
#define SMSH 40
#define GEMM_SMEM (4 * 128 * SMSH * 2 * 2)   // 81920 bytes
template<bool GELU, bool HASB, bool RES, bool OUTH, bool QSC>
__global__ __launch_bounds__(256, 2) void mma_gemm_h(
    const __half* __restrict__ A, const __half* __restrict__ W,
    const float* __restrict__ bias, const float* __restrict__ res,
    void* __restrict__ Cv, int M, int Nd, int K)
{
    extern __shared__ __half dsm[];
    __half* Asb = dsm;
    __half* Bsb = dsm + 4 * 128 * SMSH;
    const int tid  = threadIdx.x;
    const int lane = tid & 31, warp = tid >> 5;
    const int wm = warp >> 2, wn = warp & 3;
    const int lq = lane >> 2, lr = lane & 3;
    const int bm = blockIdx.y * 128, bn = blockIdx.x * 128;
    const int ntiles = K >> 5;

    const int lrow0 = tid >> 2, lc8 = (tid & 3) * 8;
    const int lrow1 = (tid + 256) >> 2;

    const int arow = ((lane >> 3) & 1) * 8 + (lane & 7);
    const int acol = (lane >> 4) * 8;
    const int brow = ((lane >> 4) << 3) + (lane & 7);
    const int bcol = ((lane >> 3) & 1) * 8;

    #define ISSUE(kt, buf)                                                       \
    {                                                                            \
        __half* asb = Asb + (buf) * 128 * SMSH;                                  \
        __half* bsb = Bsb + (buf) * 128 * SMSH;                                  \
        const __half* ag0 = A + (size_t)(bm + lrow0) * K + (kt) * 32 + lc8;      \
        const __half* wg0 = W + (size_t)(bn + lrow0) * K + (kt) * 32 + lc8;      \
        const __half* ag1 = A + (size_t)(bm + lrow1) * K + (kt) * 32 + lc8;      \
        const __half* wg1 = W + (size_t)(bn + lrow1) * K + (kt) * 32 + lc8;      \
        uint32_t sa0 = (uint32_t)__cvta_generic_to_shared(&asb[lrow0 * SMSH + lc8]); \
        uint32_t sb0 = (uint32_t)__cvta_generic_to_shared(&bsb[lrow0 * SMSH + lc8]); \
        uint32_t sa1 = (uint32_t)__cvta_generic_to_shared(&asb[lrow1 * SMSH + lc8]); \
        uint32_t sb1 = (uint32_t)__cvta_generic_to_shared(&bsb[lrow1 * SMSH + lc8]); \
        asm volatile("cp.async.cg.shared.global [%0], [%1], 16;" :: "r"(sa0), "l"(ag0)); \
        asm volatile("cp.async.cg.shared.global [%0], [%1], 16;" :: "r"(sb0), "l"(wg0)); \
        asm volatile("cp.async.cg.shared.global [%0], [%1], 16;" :: "r"(sa1), "l"(ag1)); \
        asm volatile("cp.async.cg.shared.global [%0], [%1], 16;" :: "r"(sb1), "l"(wg1)); \
        asm volatile("cp.async.commit_group;");                                  \
    }

    float acc[4][4][4] = {};
    ISSUE(0, 0);
    if (ntiles > 1) ISSUE(1, 1);
    if (ntiles > 2) ISSUE(2, 2);

    for (int kt = 0; kt < ntiles; kt++) {
        if (kt + 2 < ntiles)      asm volatile("cp.async.wait_group 2;");
        else if (kt + 1 < ntiles) asm volatile("cp.async.wait_group 1;");
        else                      asm volatile("cp.async.wait_group 0;");
        __syncthreads();
        if (kt + 3 < ntiles) ISSUE(kt + 3, (kt + 3) & 3);

        const __half* as = Asb + (kt & 3) * 128 * SMSH;
        const __half* bs = Bsb + (kt & 3) * 128 * SMSH;
        #pragma unroll
        for (int ks = 0; ks < 2; ks++) {
            const int c = ks * 16;
            uint32_t af[4][4], bf[4][2];
            #pragma unroll
            for (int mt = 0; mt < 4; mt++)
                ldsm_x4(af[mt], &as[(wm * 64 + mt * 16 + arow) * SMSH + c + acol]);
            #pragma unroll
            for (int np = 0; np < 2; np++) {
                uint32_t tmp[4];
                ldsm_x4(tmp, &bs[(wn * 32 + np * 16 + brow) * SMSH + c + bcol]);
                bf[np * 2][0] = tmp[0]; bf[np * 2][1] = tmp[1];
                bf[np * 2 + 1][0] = tmp[2]; bf[np * 2 + 1][1] = tmp[3];
            }
            #pragma unroll
            for (int mt = 0; mt < 4; mt++)
                #pragma unroll
                for (int nt = 0; nt < 4; nt++)
                    mma_f16(acc[mt][nt], af[mt], bf[nt]);
        }
    }
    #undef ISSUE

    #pragma unroll
    for (int mt = 0; mt < 4; mt++) {
        #pragma unroll
        for (int nt = 0; nt < 4; nt++) {
            const int row = bm + wm * 64 + mt * 16 + lq;
            const int col = bn + wn * 32 + nt * 8 + lr * 2;
            #pragma unroll
            for (int half = 0; half < 2; half++) {
                const int r = row + half * 8;
                float v0 = acc[mt][nt][half * 2 + 0];
                float v1 = acc[mt][nt][half * 2 + 1];
                if (HASB) { v0 += bias[col]; v1 += bias[col + 1]; }
                if (GELU) { v0 = gelu_f(v0); v1 = gelu_f(v1); }
                if (RES) {
                    const float* Rr = res + (size_t)r * Nd + col;
                    v0 += Rr[0]; v1 += Rr[1];
                }
                if (OUTH) {
                    if (QSC && col < 384) { v0 *= SCALE_; v1 *= SCALE_; }
                    __half2 hv = __floats2half2_rn(v0, v1);
                    *(__half2*)((__half*)Cv + (size_t)r * Nd + col) = hv;
                } else {
                    *(float2*)((float*)Cv + (size_t)r * Nd + col) = make_float2(v0, v1);
                }
            }
        }
    }
}

// ---------------- depthwise 3x3 dil-2 conv + GELU ---------------------------
__global__ __launch_bounds__(384) void dwconv_kernel(
    const __half* __restrict__ h1, __half* __restrict__ h2,
    const float* __restrict__ w, const float* __restrict__ bias)
{
    const int n = blockIdx.x;
    const int b = blockIdx.y;
    const int y = n >> 5, x = n & 31;
    const size_t base = (size_t)b * N_ * HID_;
    const int c0 = threadIdx.x * 2;

    float2 acc = make_float2(bias[c0], bias[c0 + 1]);
    const float* w0 = w + c0 * 9;
    const float* w1 = w + (c0 + 1) * 9;

    #pragma unroll
    for (int i = 0; i < 3; i++) {
        const int yy = y + 2 * i - 2;
        if (yy < 0 || yy > 31) continue;
        #pragma unroll
        for (int j = 0; j < 3; j++) {
            const int xx = x + 2 * j - 2;
            if (xx < 0 || xx > 31) continue;
            const float2 v = __half22float2(
                *(const __half2*)(h1 + base + (size_t)(yy * 32 + xx) * HID_ + c0));
            acc.x += w0[i * 3 + j] * v.x;
            acc.y += w1[i * 3 + j] * v.y;
        }
    }
    *(__half2*)(h2 + base + (size_t)n * HID_ + c0) =
        __floats2half2_rn(gelu_f(acc.x), gelu_f(acc.y));
}

// ---------------- bias precompute: one pass over (q,k), all heads -----------
__global__ __launch_bounds__(256) void bias2_kernel(
    const int* __restrict__ rel_index, const float* __restrict__ rel_table,
    const float* __restrict__ gb)
{
    const int q = blockIdx.x;
    const size_t rowi = (size_t)q * N_;
    #pragma unroll
    for (int it = 0; it < 2; it++) {
        const int k = (threadIdx.x + it * 256) * 2;
        const int2 ri = *(const int2*)(rel_index + rowi + k);
        const float2 g2 = *(const float2*)(gb + rowi + k);
        const float* t0 = rel_table + ri.x * H_;
        const float* t1 = rel_table + ri.y * H_;
        #pragma unroll
        for (int h = 0; h < H_; h++) {
            const __half2 v = __floats2half2_rn(t0[h] + g2.x, t1[h] + g2.y);
            *(__half2*)(g_biash + (size_t)h * (N_ * N_) + rowi + k) = v;
        }
    }
}

// ---------------- fp16 flash attention: smem-staged bias --------------------
#define SMSH 40
#define ATT_K(buf)  ((buf) * 64 * SMSH)
#define ATT_V(buf)  (2 * 64 * SMSH + (buf) * 64 * SMSH)
#define ATT_B(buf)  (4 * 64 * SMSH + (buf) * 128 * 72)
#define ATT_SMEM  ((4 * 64 * SMSH + 2 * 128 * 72) * 2)   // 57344 bytes
__global__ __launch_bounds__(256) void attn_mma_kernel(
    const __half* __restrict__ qkv, __half* __restrict__ att)
{
    extern __shared__ __half asm_[];
    const int q0 = blockIdx.x * 128;
    const int h  = blockIdx.y;
    const int b  = blockIdx.z;
    const int tid = threadIdx.x;
    const int lane = tid & 31, w = tid >> 5;
    const int lq = lane >> 2;
    const int lr = lane & 3;

    const size_t qbase = (size_t)b * N_ * 1152;
    const int kl = tid >> 2, d8 = (tid & 3) * 8;
    const __half* bhg = g_biash + (size_t)h * N_ * N_;

    #define AISSUE(kt, buf)                                                      \
    {                                                                            \
        const __half* src = qkv + qbase + (size_t)((kt) * 64 + kl) * 1152 + h * 32 + d8; \
        uint32_t sk = (uint32_t)__cvta_generic_to_shared(&asm_[ATT_K(buf) + kl * SMSH + d8]); \
        uint32_t sv = (uint32_t)__cvta_generic_to_shared(&asm_[ATT_V(buf) + kl * SMSH + d8]); \
        asm volatile("cp.async.cg.shared.global [%0], [%1], 16;" :: "r"(sk), "l"(src + 384)); \
        asm volatile("cp.async.cg.shared.global [%0], [%1], 16;" :: "r"(sv), "l"(src + 768)); \
        _Pragma("unroll")                                                        \
        for (int j = 0; j < 4; j++) {                                            \
            const int cid = tid + j * 256;                                       \
            const int brw = cid >> 3, c8 = cid & 7;                              \
            const __half* bsrc = bhg + (size_t)(q0 + brw) * N_ + (kt) * 64 + c8 * 8; \
            uint32_t bdst = (uint32_t)__cvta_generic_to_shared(                  \
                &asm_[ATT_B(buf) + brw * 72 + c8 * 8]);                          \
            asm volatile("cp.async.cg.shared.global [%0], [%1], 16;" :: "r"(bdst), "l"(bsrc)); \
        }                                                                        \
        asm volatile("cp.async.commit_group;");                                  \
    }

    const int brow = ((lane >> 4) << 3) + (lane & 7);
    const int bcol = ((lane >> 3) & 1) * 8;

    uint32_t qa[2][4];
    const int br0 = q0 + w * 16 + lq;
    {
        const __half* qp  = qkv + qbase + (size_t)br0 * 1152 + h * 32;
        const __half* qp8 = qp + 8 * 1152;
        #pragma unroll
        for (int ks = 0; ks < 2; ks++) {
            const int c = ks * 16 + 2 * lr;
            qa[ks][0] = *(const uint32_t*)(qp  + c);
            qa[ks][1] = *(const uint32_t*)(qp8 + c);
            qa[ks][2] = *(const uint32_t*)(qp  + c + 8);
            qa[ks][3] = *(const uint32_t*)(qp8 + c + 8);
        }
    }

    float o[4][4] = {};
    float m0 = -1e30f, m1 = -1e30f, l0 = 0.0f, l1 = 0.0f;

    AISSUE(0, 0);
    for (int kt = 0; kt < 16; kt++) {
        asm volatile("cp.async.wait_group 0;");
        __syncthreads();
        if (kt < 15) AISSUE(kt + 1, (kt + 1) & 1);

        const int buf = kt & 1;

        float s[8][4];
        #pragma unroll
        for (int nf = 0; nf < 8; nf++)
            s[nf][0] = s[nf][1] = s[nf][2] = s[nf][3] = 0.0f;
        #pragma unroll
        for (int ks = 0; ks < 2; ks++) {
            const int c = ks * 16;
            uint32_t kf[8][2];
            #pragma unroll
            for (int np = 0; np < 4; np++) {
                uint32_t tmp[4];
                ldsm_x4(tmp, &asm_[ATT_K(buf) + (np * 16 + brow) * SMSH + c + bcol]);
                kf[np * 2][0] = tmp[0]; kf[np * 2][1] = tmp[1];
                kf[np * 2 + 1][0] = tmp[2]; kf[np * 2 + 1][1] = tmp[3];
            }
            #pragma unroll
            for (int nf = 0; nf < 8; nf++)
                mma_f16(s[nf], qa[ks], kf[nf]);
        }

        const __half* bs0 = &asm_[ATT_B(buf) + (w * 16 + lq) * 72];
        const __half* bs1 = bs0 + 8 * 72;
        float nm0 = m0, nm1 = m1;
        #pragma unroll
        for (int nf = 0; nf < 8; nf++) {
            const int col = nf * 8 + lr * 2;
            const float2 b0v = __half22float2(*(const __half2*)(bs0 + col));
            const float2 b1v = __half22float2(*(const __half2*)(bs1 + col));
            s[nf][0] += b0v.x; s[nf][1] += b0v.y;
            s[nf][2] += b1v.x; s[nf][3] += b1v.y;
            nm0 = fmaxf(nm0, fmaxf(s[nf][0], s[nf][1]));
            nm1 = fmaxf(nm1, fmaxf(s[nf][2], s[nf][3]));
        }
        nm0 = fmaxf(nm0, __shfl_xor_sync(0xffffffffu, nm0, 1));
        nm0 = fmaxf(nm0, __shfl_xor_sync(0xffffffffu, nm0, 2));
        nm1 = fmaxf(nm1, __shfl_xor_sync(0xffffffffu, nm1, 1));
        nm1 = fmaxf(nm1, __shfl_xor_sync(0xffffffffu, nm1, 2));

        const float c0 = __expf(m0 - nm0), c1 = __expf(m1 - nm1);
        m0 = nm0; m1 = nm1; l0 *= c0; l1 *= c1;
        #pragma unroll
        for (int nf = 0; nf < 4; nf++) {
            o[nf][0] *= c0; o[nf][1] *= c0;
            o[nf][2] *= c1; o[nf][3] *= c1;
        }

        uint32_t ph[8][2];
        float a0 = 0.0f, a1 = 0.0f;
        #pragma unroll
        for (int nf = 0; nf < 8; nf++) {
            const __half2 x01 = __floats2half2_rn((s[nf][0] - nm0) * LOG2E_,
                                                  (s[nf][1] - nm0) * LOG2E_);
            const __half2 x23 = __floats2half2_rn((s[nf][2] - nm1) * LOG2E_,
                                                  (s[nf][3] - nm1) * LOG2E_);
            const __half2 p01 = h2exp2(x01);
            const __half2 p23 = h2exp2(x23);
            const float2 f01 = __half22float2(p01);
            const float2 f23 = __half22float2(p23);
            a0 += f01.x + f01.y;
            a1 += f23.x + f23.y;
            ph[nf][0] = *(const uint32_t*)&p01;
            ph[nf][1] = *(const uint32_t*)&p23;
        }
        a0 += __shfl_xor_sync(0xffffffffu, a0, 1);
        a0 += __shfl_xor_sync(0xffffffffu, a0, 2);
        a1 += __shfl_xor_sync(0xffffffffu, a1, 1);
        a1 += __shfl_xor_sync(0xffffffffu, a1, 2);
        l0 += a0; l1 += a1;

        #pragma unroll
        for (int kf2 = 0; kf2 < 4; kf2++) {
            uint32_t pa[4];
            pa[0] = ph[2 * kf2][0];
            pa[1] = ph[2 * kf2][1];
            pa[2] = ph[2 * kf2 + 1][0];
            pa[3] = ph[2 * kf2 + 1][1];
            #pragma unroll
            for (int nf = 0; nf < 4; nf++) {
                uint32_t b0r, b1r;
                ldsm_x2_t(b0r, b1r,
                          &asm_[ATT_V(buf) + (kf2 * 16 + (lane & 15)) * SMSH + nf * 8]);
                uint32_t bfr[2] = { b0r, b1r };
                mma_f16(o[nf], pa, bfr);
            }
        }
    }
    #undef AISSUE

    const float inv0 = 1.0f / l0, inv1 = 1.0f / l1;
    #pragma unroll
    for (int nf = 0; nf < 4; nf++) {
        const int col = h * 32 + nf * 8 + lr * 2;
        __half* o0 = att + ((size_t)b * N_ + br0) * C_ + col;
        __half* o1 = att + ((size_t)b * N_ + br0 + 8) * C_ + col;
        *(__half2*)o0 = __floats2half2_rn(o[nf][0] * inv0, o[nf][1] * inv0);
        *(__half2*)o1 = __floats2half2_rn(o[nf][2] * inv1, o[nf][3] * inv1);
    }
}

// ---------------- launch ----------------
extern "C" void kernel_launch(void* const* d_in, const int* in_sizes, int n_in,
                              void* d_out, int out_size)
{
    const int base = (n_in >= 19) ? 2 : 0;
    const float* x         = (const float*)d_in[0];
    const int*   rel_index = (const int*)  d_in[1 + base];
    const float* ln1_g     = (const float*)d_in[2 + base];
    const float* ln1_b     = (const float*)d_in[3 + base];
    const float* w_qkv     = (const float*)d_in[4 + base];
    const float* w_proj    = (const float*)d_in[5 + base];
    const float* b_proj    = (const float*)d_in[6 + base];
    const float* rel_table = (const float*)d_in[7 + base];
    const float* gbias     = (const float*)d_in[8 + base];
    const float* ln2_g     = (const float*)d_in[9 + base];
    const float* ln2_b     = (const float*)d_in[10 + base];
    const float* w_pw1     = (const float*)d_in[11 + base];
    const float* b_pw1     = (const float*)d_in[12 + base];
    const float* w_dw      = (const float*)d_in[13 + base];
    const float* b_dw      = (const float*)d_in[14 + base];
    const float* w_pw2     = (const float*)d_in[15 + base];
    const float* b_pw2     = (const float*)d_in[16 + base];
    float* out = (float*)d_out;

    void *p_ln2, *p_h1, *p_h2, *p_x1, *p_ln1, *p_qkvh, *p_atth, *p_wh;
    cudaGetSymbolAddress(&p_ln2, g_ln2);
    cudaGetSymbolAddress(&p_h1,  g_h1);
    cudaGetSymbolAddress(&p_h2,  g_h2);
    cudaGetSymbolAddress(&p_x1,  g_x1);
    cudaGetSymbolAddress(&p_ln1, g_ln1);
    cudaGetSymbolAddress(&p_qkvh, g_qkvh);
    cudaGetSymbolAddress(&p_atth, g_atth);
    cudaGetSymbolAddress(&p_wh,  g_wh);
    __half* wh = (__half*)p_wh;

    static bool attr_done = false;
    if (!attr_done) {
        cudaFuncSetAttribute(mma_gemm_h<true, true, false, true, false>,
                             cudaFuncAttributeMaxDynamicSharedMemorySize, GEMM_SMEM);
        cudaFuncSetAttribute(mma_gemm_h<false, true, true, false, false>,
                             cudaFuncAttributeMaxDynamicSharedMemorySize, GEMM_SMEM);
        cudaFuncSetAttribute(mma_gemm_h<false, false, false, true, true>,
                             cudaFuncAttributeMaxDynamicSharedMemorySize, GEMM_SMEM);
        cudaFuncSetAttribute(attn_mma_kernel,
                             cudaFuncAttributeMaxDynamicSharedMemorySize, ATT_SMEM);
        attr_done = true;
    }

    w2h_all_kernel<<<(Q_END + 255) / 256, 256>>>(w_qkv, w_pw1, w_pw2, w_proj, wh);
    bias2_kernel<<<N_, 256>>>(rel_index, rel_table, gbias);

    // 1) x1 = x + MLP(LN2(x))
    ln_kernel<<<M_ / 8, 256>>>(x, ln2_g, ln2_b, (__half*)p_ln2);
    mma_gemm_h<true, true, false, true, false><<<dim3(HID_ / 128, M_ / 128), 256, GEMM_SMEM>>>(
        (const __half*)p_ln2, wh + OFF_PW1, b_pw1, nullptr, p_h1, M_, HID_, C_);
    dwconv_kernel<<<dim3(N_, B_), 384>>>(
        (const __half*)p_h1, (__half*)p_h2, w_dw, b_dw);
    mma_gemm_h<false, true, true, false, false><<<dim3(C_ / 128, M_ / 128), 256, GEMM_SMEM>>>(
        (const __half*)p_h2, wh + OFF_PW2, b_pw2, x, p_x1, M_, C_, HID_);

    // 2) out = x1 + Attn(LN1(x1))
    ln_kernel<<<M_ / 8, 256>>>((const float*)p_x1, ln1_g, ln1_b, (__half*)p_ln1);
    mma_gemm_h<false, false, false, true, true><<<dim3(1152 / 128, M_ / 128), 256, GEMM_SMEM>>>(
        (const __half*)p_ln1, wh + OFF_QKV, nullptr, nullptr, p_qkvh, M_, 1152, C_);
    attn_mma_kernel<<<dim3(N_ / 128, H_, B_), 256, ATT_SMEM>>>(
        (const __half*)p_qkvh, (__half*)p_atth);
    mma_gemm_h<false, true, true, false, false><<<dim3(C_ / 128, M_ / 128), 256, GEMM_SMEM>>>(
        (const __half*)p_atth, wh + OFF_PROJ, b_proj, (const float*)p_x1, out, M_, C_, C_);
}

// round 15
// speedup vs baseline: 1.0008x; 1.0008x over previous
#include <cuda_runtime.h>
#include <cuda_fp16.h>
#include <math.h>
#include <stdint.h>

// Problem constants
#define B_  8
#define N_  1024
#define C_  384
#define H_  12
#define HD_ 32
#define HID_ 768
#define M_  (B_ * N_)
#define NREL_ 3969
#define SCALE_ 0.17677669529663687f
#define LOG2E_ 1.4426950408889634f

// NOTE: harness PTX target is sm_103 (no 'a') -> tcgen05.* unavailable.

__device__ __forceinline__ float gelu_f(float v) {
    return 0.5f * v * (1.0f + erff(v * 0.70710678118654752f));
}

__device__ __forceinline__ void mma_f16(float* c, const uint32_t* a, const uint32_t* b) {
    asm volatile(
        "mma.sync.aligned.m16n8k16.row.col.f32.f16.f16.f32 "
        "{%0,%1,%2,%3}, {%4,%5,%6,%7}, {%8,%9}, {%0,%1,%2,%3};"
        : "+f"(c[0]), "+f"(c[1]), "+f"(c[2]), "+f"(c[3])
        : "r"(a[0]), "r"(a[1]), "r"(a[2]), "r"(a[3]), "r"(b[0]), "r"(b[1]));
}

__device__ __forceinline__ void ldsm_x4(uint32_t* r, const __half* p) {
    uint32_t addr = (uint32_t)__cvta_generic_to_shared(p);
    asm volatile("ldmatrix.sync.aligned.m8n8.x4.shared.b16 {%0,%1,%2,%3}, [%4];"
                 : "=r"(r[0]), "=r"(r[1]), "=r"(r[2]), "=r"(r[3]) : "r"(addr));
}

__device__ __forceinline__ void ldsm_x2_t(uint32_t& r0, uint32_t& r1, const __half* p) {
    uint32_t addr = (uint32_t)__cvta_generic_to_shared(p);
    asm volatile("ldmatrix.sync.aligned.m8n8.x2.trans.shared.b16 {%0,%1}, [%2];"
                 : "=r"(r0), "=r"(r1) : "r"(addr));
}

// ---------------- scratch ----------------
__device__ __align__(16) __half g_ln2[M_ * C_];
__device__ __align__(16) __half g_h1 [M_ * HID_];
__device__ __align__(16) __half g_h2 [M_ * HID_];
__device__ float g_x1 [M_ * C_];
__device__ __align__(16) __half g_ln1[M_ * C_];
__device__ __align__(16) __half g_qkvh[M_ * 3 * C_];
__device__ __align__(16) __half g_atth[M_ * C_];
__device__ __align__(16) __half g_biash[H_ * N_ * N_];
__device__ __align__(16) __half g_wh[1179648];
#define OFF_QKV  0
#define OFF_PW1  442368
#define OFF_PW2  737280
#define OFF_PROJ 1032192
#define Q_QKV  110592
#define Q_PW1  184320
#define Q_PW2  258048
#define Q_END  294912

// ---------------- merged weight fp32 -> fp16 ----------------
__global__ __launch_bounds__(256) void w2h_all_kernel(
    const float* __restrict__ s_qkv, const float* __restrict__ s_pw1,
    const float* __restrict__ s_pw2, const float* __restrict__ s_proj,
    __half* __restrict__ dst)
{
    const int i = blockIdx.x * 256 + threadIdx.x;
    if (i >= Q_END) return;
    const float* src; int local;
    if (i < Q_QKV)      { src = s_qkv;  local = i; }
    else if (i < Q_PW1) { src = s_pw1;  local = i - Q_QKV; }
    else if (i < Q_PW2) { src = s_pw2;  local = i - Q_PW1; }
    else                { src = s_proj; local = i - Q_PW2; }
    const float4 v = ((const float4*)src)[local];
    __half2 h0 = __floats2half2_rn(v.x, v.y);
    __half2 h1 = __floats2half2_rn(v.z, v.w);
    uint2 u; u.x = *(uint32_t*)&h0; u.y = *(uint32_t*)&h1;
    *(uint2*)(dst + (size_t)i * 4) = u;
}

// ---------------- LayerNorm: warp-per-row, shfl-only -------------------------
__global__ __launch_bounds__(256) void ln_kernel(
    const float* __restrict__ in, const float* __restrict__ g,
    const float* __restrict__ bta, __half* __restrict__ out)
{
    const int lane = threadIdx.x & 31;
    const int row  = blockIdx.x * 8 + (threadIdx.x >> 5);
    const float4* xr = (const float4*)(in + (size_t)row * C_);
    const float4 a = xr[lane], b = xr[lane + 32], c = xr[lane + 64];

    float s = (a.x + a.y) + (a.z + a.w) + (b.x + b.y) + (b.z + b.w)
            + (c.x + c.y) + (c.z + c.w);
    #pragma unroll
    for (int o = 16; o; o >>= 1) s += __shfl_xor_sync(0xffffffffu, s, o);
    const float mean = s * (1.0f / C_);

    const float dx[12] = { a.x - mean, a.y - mean, a.z - mean, a.w - mean,
                           b.x - mean, b.y - mean, b.z - mean, b.w - mean,
                           c.x - mean, c.y - mean, c.z - mean, c.w - mean };
    float q = 0.0f;
    #pragma unroll
    for (int i = 0; i < 12; i++) q += dx[i] * dx[i];
    #pragma unroll
    for (int o = 16; o; o >>= 1) q += __shfl_xor_sync(0xffffffffu, q, o);
    const float inv = rsqrtf(q * (1.0f / C_) + 1e-5f);

    const float4* g4 = (const float4*)g;
    const float4* t4 = (const float4*)bta;
    __half* orow = out + (size_t)row * C_;
    #pragma unroll
    for (int seg = 0; seg < 3; seg++) {
        const float4 gv = g4[lane + seg * 32];
        const float4 tv = t4[lane + seg * 32];
        const float* d = &dx[seg * 4];
        __half2 h0 = __floats2half2_rn(d[0] * inv * gv.x + tv.x,
                                       d[1] * inv * gv.y + tv.y);
        __half2 h1 = __floats2half2_rn(d[2] * inv * gv.z + tv.z,
                                       d[3] * inv * gv.w + tv.w);
        uint2 u; u.x = *(uint32_t*)&h0; u.y = *(uint32_t*)&h1;
        *(uint2*)(orow + lane * 4 + seg * 128) = u;
    }
}

// ---------------- fp16 GEMM: CTA 128x64, warp 32x32, 3 CTA/SM ---------------
// 4-stage cp.async pipeline, 1 barrier/iter. A tile 128 rows, B tile 64 rows.
#define SMSH 40
#define AST (128 * SMSH)             // A stage stride (halves)
#define BST (64 * SMSH)              // B stage stride (halves)
#define GEMM_SMEM (4 * (AST + BST) * 2)   // 61440 bytes
template<bool GELU, bool HASB, bool RES, bool OUTH, bool QSC>
__global__ __launch_bounds__(256, 3) void mma_gemm_h(
    const __half* __restrict__ A, const __half* __restrict__ W,
    const float* __restrict__ bias, const float* __restrict__ res,
    void* __restrict__ Cv, int M, int Nd, int K)
{
    extern __shared__ __half dsm[];
    __half* Asb = dsm;                  // 4 stages of A
    __half* Bsb = dsm + 4 * AST;        // 4 stages of B
    const int tid  = threadIdx.x;
    const int lane = tid & 31, warp = tid >> 5;
    const int wm = warp >> 1, wn = warp & 1;   // 4 x 2 warps, tile 32x32
    const int lq = lane >> 2, lr = lane & 3;
    const int bm = blockIdx.y * 128, bn = blockIdx.x * 64;
    const int ntiles = K >> 5;

    const int lrow0 = tid >> 2, lc8 = (tid & 3) * 8;   // 0..63 rows
    const int lrow1 = lrow0 + 64;                      // 64..127 (A only)

    const int arow = ((lane >> 3) & 1) * 8 + (lane & 7);
    const int acol = (lane >> 4) * 8;
    const int brow = ((lane >> 4) << 3) + (lane & 7);
    const int bcol = ((lane >> 3) & 1) * 8;

    #define ISSUE(kt, buf)                                                       \
    {                                                                            \
        __half* asb = Asb + (buf) * AST;                                         \
        __half* bsb = Bsb + (buf) * BST;                                         \
        const __half* ag0 = A + (size_t)(bm + lrow0) * K + (kt) * 32 + lc8;      \
        const __half* ag1 = A + (size_t)(bm + lrow1) * K + (kt) * 32 + lc8;      \
        const __half* wg0 = W + (size_t)(bn + lrow0) * K + (kt) * 32 + lc8;      \
        uint32_t sa0 = (uint32_t)__cvta_generic_to_shared(&asb[lrow0 * SMSH + lc8]); \
        uint32_t sa1 = (uint32_t)__cvta_generic_to_shared(&asb[lrow1 * SMSH + lc8]); \
        uint32_t sb0 = (uint32_t)__cvta_generic_to_shared(&bsb[lrow0 * SMSH + lc8]); \
        asm volatile("cp.async.cg.shared.global [%0], [%1], 16;" :: "r"(sa0), "l"(ag0)); \
        asm volatile("cp.async.cg.shared.global [%0], [%1], 16;" :: "r"(sa1), "l"(ag1)); \
        asm volatile("cp.async.cg.shared.global [%0], [%1], 16;" :: "r"(sb0), "l"(wg0)); \
        asm volatile("cp.async.commit_group;");                                  \
    }

    float acc[2][4][4] = {};
    ISSUE(0, 0);
    if (ntiles > 1) ISSUE(1, 1);
    if (ntiles > 2) ISSUE(2, 2);

    for (int kt = 0; kt < ntiles; kt++) {
        if (kt + 2 < ntiles)      asm volatile("cp.async.wait_group 2;");
        else if (kt + 1 < ntiles) asm volatile("cp.async.wait_group 1;");
        else                      asm volatile("cp.async.wait_group 0;");
        __syncthreads();
        if (kt + 3 < ntiles) ISSUE(kt + 3, (kt + 3) & 3);

        const __half* as = Asb + (kt & 3) * AST;
        const __half* bs = Bsb + (kt & 3) * BST;
        #pragma unroll
        for (int ks = 0; ks < 2; ks++) {
            const int c = ks * 16;
            uint32_t af[2][4], bf[4][2];
            #pragma unroll
            for (int mt = 0; mt < 2; mt++)
                ldsm_x4(af[mt], &as[(wm * 32 + mt * 16 + arow) * SMSH + c + acol]);
            #pragma unroll
            for (int np = 0; np < 2; np++) {
                uint32_t tmp[4];
                ldsm_x4(tmp, &bs[(wn * 32 + np * 16 + brow) * SMSH + c + bcol]);
                bf[np * 2][0] = tmp[0]; bf[np * 2][1] = tmp[1];
                bf[np * 2 + 1][0] = tmp[2]; bf[np * 2 + 1][1] = tmp[3];
            }
            #pragma unroll
            for (int mt = 0; mt < 2; mt++)
                #pragma unroll
                for (int nt = 0; nt < 4; nt++)
                    mma_f16(acc[mt][nt], af[mt], bf[nt]);
        }
    }
    #undef ISSUE

    #pragma unroll
    for (int mt = 0; mt < 2; mt++) {
        #pragma unroll
        for (int nt = 0; nt < 4; nt++) {
            const int row = bm + wm * 32 + mt * 16 + lq;
            const int col = bn + wn * 32 + nt * 8 + lr * 2;
            #pragma unroll
            for (int half = 0; half < 2; half++) {
                const int r = row + half * 8;
                float v0 = acc[mt][nt][half * 2 + 0];
                float v1 = acc[mt][nt][half * 2 + 1];
                if (HASB) { v0 += bias[col]; v1 += bias[col + 1]; }
                if (GELU) { v0 = gelu_f(v0); v1 = gelu_f(v1); }
                if (RES) {
                    const float* Rr = res + (size_t)r * Nd + col;
                    v0 += Rr[0]; v1 += Rr[1];
                }
                if (OUTH) {
                    if (QSC && col < 384) { v0 *= SCALE_; v1 *= SCALE_; }
                    __half2 hv = __floats2half2_rn(v0, v1);
                    *(__half2*)((__half*)Cv + (size_t)r * Nd + col) = hv;
                } else {
                    *(float2*)((float*)Cv + (size_t)r * Nd + col) = make_float2(v0, v1);
                }
            }
        }
    }
}

// ---------------- depthwise 3x3 dil-2 conv + GELU ---------------------------
__global__ __launch_bounds__(384) void dwconv_kernel(
    const __half* __restrict__ h1, __half* __restrict__ h2,
    const float* __restrict__ w, const float* __restrict__ bias)
{
    const int n = blockIdx.x;
    const int b = blockIdx.y;
    const int y = n >> 5, x = n & 31;
    const size_t base = (size_t)b * N_ * HID_;
    const int c0 = threadIdx.x * 2;

    float2 acc = make_float2(bias[c0], bias[c0 + 1]);
    const float* w0 = w + c0 * 9;
    const float* w1 = w + (c0 + 1) * 9;

    #pragma unroll
    for (int i = 0; i < 3; i++) {
        const int yy = y + 2 * i - 2;
        if (yy < 0 || yy > 31) continue;
        #pragma unroll
        for (int j = 0; j < 3; j++) {
            const int xx = x + 2 * j - 2;
            if (xx < 0 || xx > 31) continue;
            const float2 v = __half22float2(
                *(const __half2*)(h1 + base + (size_t)(yy * 32 + xx) * HID_ + c0));
            acc.x += w0[i * 3 + j] * v.x;
            acc.y += w1[i * 3 + j] * v.y;
        }
    }
    *(__half2*)(h2 + base + (size_t)n * HID_ + c0) =
        __floats2half2_rn(gelu_f(acc.x), gelu_f(acc.y));
}

// ---------------- bias precompute: one pass over (q,k), all heads -----------
__global__ __launch_bounds__(256) void bias2_kernel(
    const int* __restrict__ rel_index, const float* __restrict__ rel_table,
    const float* __restrict__ gb)
{
    const int q = blockIdx.x;
    const size_t rowi = (size_t)q * N_;
    #pragma unroll
    for (int it = 0; it < 2; it++) {
        const int k = (threadIdx.x + it * 256) * 2;
        const int2 ri = *(const int2*)(rel_index + rowi + k);
        const float2 g2 = *(const float2*)(gb + rowi + k);
        const float* t0 = rel_table + ri.x * H_;
        const float* t1 = rel_table + ri.y * H_;
        #pragma unroll
        for (int h = 0; h < H_; h++) {
            const __half2 v = __floats2half2_rn(t0[h] + g2.x, t1[h] + g2.y);
            *(__half2*)(g_biash + (size_t)h * (N_ * N_) + rowi + k) = v;
        }
    }
}

// ---------------- fp16 flash attention: smem-staged bias --------------------
#define ATT_K(buf)  ((buf) * 64 * SMSH)
#define ATT_V(buf)  (2 * 64 * SMSH + (buf) * 64 * SMSH)
#define ATT_B(buf)  (4 * 64 * SMSH + (buf) * 128 * 72)
#define ATT_SMEM  ((4 * 64 * SMSH + 2 * 128 * 72) * 2)   // 57344 bytes
__global__ __launch_bounds__(256) void attn_mma_kernel(
    const __half* __restrict__ qkv, __half* __restrict__ att)
{
    extern __shared__ __half asm_[];
    const int q0 = blockIdx.x * 128;
    const int h  = blockIdx.y;
    const int b  = blockIdx.z;
    const int tid = threadIdx.x;
    const int lane = tid & 31, w = tid >> 5;
    const int lq = lane >> 2;
    const int lr = lane & 3;

    const size_t qbase = (size_t)b * N_ * 1152;
    const int kl = tid >> 2, d8 = (tid & 3) * 8;
    const __half* bhg = g_biash + (size_t)h * N_ * N_;

    #define AISSUE(kt, buf)                                                      \
    {                                                                            \
        const __half* src = qkv + qbase + (size_t)((kt) * 64 + kl) * 1152 + h * 32 + d8; \
        uint32_t sk = (uint32_t)__cvta_generic_to_shared(&asm_[ATT_K(buf) + kl * SMSH + d8]); \
        uint32_t sv = (uint32_t)__cvta_generic_to_shared(&asm_[ATT_V(buf) + kl * SMSH + d8]); \
        asm volatile("cp.async.cg.shared.global [%0], [%1], 16;" :: "r"(sk), "l"(src + 384)); \
        asm volatile("cp.async.cg.shared.global [%0], [%1], 16;" :: "r"(sv), "l"(src + 768)); \
        _Pragma("unroll")                                                        \
        for (int j = 0; j < 4; j++) {                                            \
            const int cid = tid + j * 256;                                       \
            const int brw = cid >> 3, c8 = cid & 7;                              \
            const __half* bsrc = bhg + (size_t)(q0 + brw) * N_ + (kt) * 64 + c8 * 8; \
            uint32_t bdst = (uint32_t)__cvta_generic_to_shared(                  \
                &asm_[ATT_B(buf) + brw * 72 + c8 * 8]);                          \
            asm volatile("cp.async.cg.shared.global [%0], [%1], 16;" :: "r"(bdst), "l"(bsrc)); \
        }                                                                        \
        asm volatile("cp.async.commit_group;");                                  \
    }

    const int brow = ((lane >> 4) << 3) + (lane & 7);
    const int bcol = ((lane >> 3) & 1) * 8;

    uint32_t qa[2][4];
    const int br0 = q0 + w * 16 + lq;
    {
        const __half* qp  = qkv + qbase + (size_t)br0 * 1152 + h * 32;
        const __half* qp8 = qp + 8 * 1152;
        #pragma unroll
        for (int ks = 0; ks < 2; ks++) {
            const int c = ks * 16 + 2 * lr;
            qa[ks][0] = *(const uint32_t*)(qp  + c);
            qa[ks][1] = *(const uint32_t*)(qp8 + c);
            qa[ks][2] = *(const uint32_t*)(qp  + c + 8);
            qa[ks][3] = *(const uint32_t*)(qp8 + c + 8);
        }
    }

    float o[4][4] = {};
    float m0 = -1e30f, m1 = -1e30f, l0 = 0.0f, l1 = 0.0f;

    AISSUE(0, 0);
    for (int kt = 0; kt < 16; kt++) {
        asm volatile("cp.async.wait_group 0;");
        __syncthreads();
        if (kt < 15) AISSUE(kt + 1, (kt + 1) & 1);

        const int buf = kt & 1;

        float s[8][4];
        #pragma unroll
        for (int nf = 0; nf < 8; nf++)
            s[nf][0] = s[nf][1] = s[nf][2] = s[nf][3] = 0.0f;
        #pragma unroll
        for (int ks = 0; ks < 2; ks++) {
            const int c = ks * 16;
            uint32_t kf[8][2];
            #pragma unroll
            for (int np = 0; np < 4; np++) {
                uint32_t tmp[4];
                ldsm_x4(tmp, &asm_[ATT_K(buf) + (np * 16 + brow) * SMSH + c + bcol]);
                kf[np * 2][0] = tmp[0]; kf[np * 2][1] = tmp[1];
                kf[np * 2 + 1][0] = tmp[2]; kf[np * 2 + 1][1] = tmp[3];
            }
            #pragma unroll
            for (int nf = 0; nf < 8; nf++)
                mma_f16(s[nf], qa[ks], kf[nf]);
        }

        const __half* bs0 = &asm_[ATT_B(buf) + (w * 16 + lq) * 72];
        const __half* bs1 = bs0 + 8 * 72;
        float nm0 = m0, nm1 = m1;
        #pragma unroll
        for (int nf = 0; nf < 8; nf++) {
            const int col = nf * 8 + lr * 2;
            const float2 b0v = __half22float2(*(const __half2*)(bs0 + col));
            const float2 b1v = __half22float2(*(const __half2*)(bs1 + col));
            s[nf][0] += b0v.x; s[nf][1] += b0v.y;
            s[nf][2] += b1v.x; s[nf][3] += b1v.y;
            nm0 = fmaxf(nm0, fmaxf(s[nf][0], s[nf][1]));
            nm1 = fmaxf(nm1, fmaxf(s[nf][2], s[nf][3]));
        }
        nm0 = fmaxf(nm0, __shfl_xor_sync(0xffffffffu, nm0, 1));
        nm0 = fmaxf(nm0, __shfl_xor_sync(0xffffffffu, nm0, 2));
        nm1 = fmaxf(nm1, __shfl_xor_sync(0xffffffffu, nm1, 1));
        nm1 = fmaxf(nm1, __shfl_xor_sync(0xffffffffu, nm1, 2));

        const float c0 = __expf(m0 - nm0), c1 = __expf(m1 - nm1);
        m0 = nm0; m1 = nm1; l0 *= c0; l1 *= c1;
        #pragma unroll
        for (int nf = 0; nf < 4; nf++) {
            o[nf][0] *= c0; o[nf][1] *= c0;
            o[nf][2] *= c1; o[nf][3] *= c1;
        }

        uint32_t ph[8][2];
        float a0 = 0.0f, a1 = 0.0f;
        #pragma unroll
        for (int nf = 0; nf < 8; nf++) {
            const __half2 x01 = __floats2half2_rn((s[nf][0] - nm0) * LOG2E_,
                                                  (s[nf][1] - nm0) * LOG2E_);
            const __half2 x23 = __floats2half2_rn((s[nf][2] - nm1) * LOG2E_,
                                                  (s[nf][3] - nm1) * LOG2E_);
            const __half2 p01 = h2exp2(x01);
            const __half2 p23 = h2exp2(x23);
            const float2 f01 = __half22float2(p01);
            const float2 f23 = __half22float2(p23);
            a0 += f01.x + f01.y;
            a1 += f23.x + f23.y;
            ph[nf][0] = *(const uint32_t*)&p01;
            ph[nf][1] = *(const uint32_t*)&p23;
        }
        a0 += __shfl_xor_sync(0xffffffffu, a0, 1);
        a0 += __shfl_xor_sync(0xffffffffu, a0, 2);
        a1 += __shfl_xor_sync(0xffffffffu, a1, 1);
        a1 += __shfl_xor_sync(0xffffffffu, a1, 2);
        l0 += a0; l1 += a1;

        #pragma unroll
        for (int kf2 = 0; kf2 < 4; kf2++) {
            uint32_t pa[4];
            pa[0] = ph[2 * kf2][0];
            pa[1] = ph[2 * kf2][1];
            pa[2] = ph[2 * kf2 + 1][0];
            pa[3] = ph[2 * kf2 + 1][1];
            #pragma unroll
            for (int nf = 0; nf < 4; nf++) {
                uint32_t b0r, b1r;
                ldsm_x2_t(b0r, b1r,
                          &asm_[ATT_V(buf) + (kf2 * 16 + (lane & 15)) * SMSH + nf * 8]);
                uint32_t bfr[2] = { b0r, b1r };
                mma_f16(o[nf], pa, bfr);
            }
        }
    }
    #undef AISSUE

    const float inv0 = 1.0f / l0, inv1 = 1.0f / l1;
    #pragma unroll
    for (int nf = 0; nf < 4; nf++) {
        const int col = h * 32 + nf * 8 + lr * 2;
        __half* o0 = att + ((size_t)b * N_ + br0) * C_ + col;
        __half* o1 = att + ((size_t)b * N_ + br0 + 8) * C_ + col;
        *(__half2*)o0 = __floats2half2_rn(o[nf][0] * inv0, o[nf][1] * inv0);
        *(__half2*)o1 = __floats2half2_rn(o[nf][2] * inv1, o[nf][3] * inv1);
    }
}

// ---------------- launch ----------------
extern "C" void kernel_launch(void* const* d_in, const int* in_sizes, int n_in,
                              void* d_out, int out_size)
{
    const int base = (n_in >= 19) ? 2 : 0;
    const float* x         = (const float*)d_in[0];
    const int*   rel_index = (const int*)  d_in[1 + base];
    const float* ln1_g     = (const float*)d_in[2 + base];
    const float* ln1_b     = (const float*)d_in[3 + base];
    const float* w_qkv     = (const float*)d_in[4 + base];
    const float* w_proj    = (const float*)d_in[5 + base];
    const float* b_proj    = (const float*)d_in[6 + base];
    const float* rel_table = (const float*)d_in[7 + base];
    const float* gbias     = (const float*)d_in[8 + base];
    const float* ln2_g     = (const float*)d_in[9 + base];
    const float* ln2_b     = (const float*)d_in[10 + base];
    const float* w_pw1     = (const float*)d_in[11 + base];
    const float* b_pw1     = (const float*)d_in[12 + base];
    const float* w_dw      = (const float*)d_in[13 + base];
    const float* b_dw      = (const float*)d_in[14 + base];
    const float* w_pw2     = (const float*)d_in[15 + base];
    const float* b_pw2     = (const float*)d_in[16 + base];
    float* out = (float*)d_out;

    void *p_ln2, *p_h1, *p_h2, *p_x1, *p_ln1, *p_qkvh, *p_atth, *p_wh;
    cudaGetSymbolAddress(&p_ln2, g_ln2);
    cudaGetSymbolAddress(&p_h1,  g_h1);
    cudaGetSymbolAddress(&p_h2,  g_h2);
    cudaGetSymbolAddress(&p_x1,  g_x1);
    cudaGetSymbolAddress(&p_ln1, g_ln1);
    cudaGetSymbolAddress(&p_qkvh, g_qkvh);
    cudaGetSymbolAddress(&p_atth, g_atth);
    cudaGetSymbolAddress(&p_wh,  g_wh);
    __half* wh = (__half*)p_wh;

    static bool attr_done = false;
    if (!attr_done) {
        cudaFuncSetAttribute(mma_gemm_h<true, true, false, true, false>,
                             cudaFuncAttributeMaxDynamicSharedMemorySize, GEMM_SMEM);
        cudaFuncSetAttribute(mma_gemm_h<false, true, true, false, false>,
                             cudaFuncAttributeMaxDynamicSharedMemorySize, GEMM_SMEM);
        cudaFuncSetAttribute(mma_gemm_h<false, false, false, true, true>,
                             cudaFuncAttributeMaxDynamicSharedMemorySize, GEMM_SMEM);
        cudaFuncSetAttribute(attn_mma_kernel,
                             cudaFuncAttributeMaxDynamicSharedMemorySize, ATT_SMEM);
        attr_done = true;
    }

    w2h_all_kernel<<<(Q_END + 255) / 256, 256>>>(w_qkv, w_pw1, w_pw2, w_proj, wh);
    bias2_kernel<<<N_, 256>>>(rel_index, rel_table, gbias);

    // 1) x1 = x + MLP(LN2(x))
    ln_kernel<<<M_ / 8, 256>>>(x, ln2_g, ln2_b, (__half*)p_ln2);
    mma_gemm_h<true, true, false, true, false><<<dim3(HID_ / 64, M_ / 128), 256, GEMM_SMEM>>>(
        (const __half*)p_ln2, wh + OFF_PW1, b_pw1, nullptr, p_h1, M_, HID_, C_);
    dwconv_kernel<<<dim3(N_, B_), 384>>>(
        (const __half*)p_h1, (__half*)p_h2, w_dw, b_dw);
    mma_gemm_h<false, true, true, false, false><<<dim3(C_ / 64, M_ / 128), 256, GEMM_SMEM>>>(
        (const __half*)p_h2, wh + OFF_PW2, b_pw2, x, p_x1, M_, C_, HID_);

    // 2) out = x1 + Attn(LN1(x1))
    ln_kernel<<<M_ / 8, 256>>>((const float*)p_x1, ln1_g, ln1_b, (__half*)p_ln1);
    mma_gemm_h<false, false, false, true, true><<<dim3(1152 / 64, M_ / 128), 256, GEMM_SMEM>>>(
        (const __half*)p_ln1, wh + OFF_QKV, nullptr, nullptr, p_qkvh, M_, 1152, C_);
    attn_mma_kernel<<<dim3(N_ / 128, H_, B_), 256, ATT_SMEM>>>(
        (const __half*)p_qkvh, (__half*)p_atth);
    mma_gemm_h<false, true, true, false, false><<<dim3(C_ / 64, M_ / 128), 256, GEMM_SMEM>>>(
        (const __half*)p_atth, wh + OFF_PROJ, b_proj, (const float*)p_x1, out, M_, C_, C_);
}

// round 16
// speedup vs baseline: 1.0275x; 1.0267x over previous
#include <cuda_runtime.h>
#include <cuda_fp16.h>
#include <math.h>
#include <stdint.h>

// Problem constants
#define B_  8
#define N_  1024
#define C_  384
#define H_  12
#define HD_ 32
#define HID_ 768
#define M_  (B_ * N_)
#define NREL_ 3969
#define SCALE_ 0.17677669529663687f
#define LOG2E_ 1.4426950408889634f

// NOTE: harness PTX target is sm_103 (no 'a') -> tcgen05.* unavailable.
// GEMMs are HMMA-issue-bound (~150 TF/s floor on mma.sync path).

__device__ __forceinline__ float gelu_f(float v) {
    return 0.5f * v * (1.0f + erff(v * 0.70710678118654752f));
}

__device__ __forceinline__ void mma_f16(float* c, const uint32_t* a, const uint32_t* b) {
    asm volatile(
        "mma.sync.aligned.m16n8k16.row.col.f32.f16.f16.f32 "
        "{%0,%1,%2,%3}, {%4,%5,%6,%7}, {%8,%9}, {%0,%1,%2,%3};"
        : "+f"(c[0]), "+f"(c[1]), "+f"(c[2]), "+f"(c[3])
        : "r"(a[0]), "r"(a[1]), "r"(a[2]), "r"(a[3]), "r"(b[0]), "r"(b[1]));
}

__device__ __forceinline__ void ldsm_x4(uint32_t* r, const __half* p) {
    uint32_t addr = (uint32_t)__cvta_generic_to_shared(p);
    asm volatile("ldmatrix.sync.aligned.m8n8.x4.shared.b16 {%0,%1,%2,%3}, [%4];"
                 : "=r"(r[0]), "=r"(r[1]), "=r"(r[2]), "=r"(r[3]) : "r"(addr));
}

__device__ __forceinline__ void ldsm_x2_t(uint32_t& r0, uint32_t& r1, const __half* p) {
    uint32_t addr = (uint32_t)__cvta_generic_to_shared(p);
    asm volatile("ldmatrix.sync.aligned.m8n8.x2.trans.shared.b16 {%0,%1}, [%2];"
                 : "=r"(r0), "=r"(r1) : "r"(addr));
}

// ---------------- scratch ----------------
__device__ __align__(16) __half g_ln2[M_ * C_];
__device__ __align__(16) __half g_h1 [M_ * HID_];
__device__ __align__(16) __half g_h2 [M_ * HID_];
__device__ float g_x1 [M_ * C_];
__device__ __align__(16) __half g_ln1[M_ * C_];
__device__ __align__(16) __half g_qkvh[M_ * 3 * C_];
__device__ __align__(16) __half g_atth[M_ * C_];
__device__ __align__(16) __half g_biash[H_ * N_ * N_];
__device__ __align__(16) __half g_wh[1179648];
#define OFF_QKV  0
#define OFF_PW1  442368
#define OFF_PW2  737280
#define OFF_PROJ 1032192
#define Q_QKV  110592
#define Q_PW1  184320
#define Q_PW2  258048
#define Q_END  294912
#define PREP_W2H_BLOCKS ((Q_END + 255) / 256)   // 1152

// ---------------- merged prep: weight f32->f16 + bias precompute ------------
__global__ __launch_bounds__(256) void prep_kernel(
    const float* __restrict__ s_qkv, const float* __restrict__ s_pw1,
    const float* __restrict__ s_pw2, const float* __restrict__ s_proj,
    __half* __restrict__ dst,
    const int* __restrict__ rel_index, const float* __restrict__ rel_table,
    const float* __restrict__ gb)
{
    if (blockIdx.x < PREP_W2H_BLOCKS) {
        const int i = blockIdx.x * 256 + threadIdx.x;
        if (i >= Q_END) return;
        const float* src; int local;
        if (i < Q_QKV)      { src = s_qkv;  local = i; }
        else if (i < Q_PW1) { src = s_pw1;  local = i - Q_QKV; }
        else if (i < Q_PW2) { src = s_pw2;  local = i - Q_PW1; }
        else                { src = s_proj; local = i - Q_PW2; }
        const float4 v = ((const float4*)src)[local];
        __half2 h0 = __floats2half2_rn(v.x, v.y);
        __half2 h1 = __floats2half2_rn(v.z, v.w);
        uint2 u; u.x = *(uint32_t*)&h0; u.y = *(uint32_t*)&h1;
        *(uint2*)(dst + (size_t)i * 4) = u;
        return;
    }
    // bias plane: one q row, all 12 heads
    const int q = blockIdx.x - PREP_W2H_BLOCKS;
    const size_t rowi = (size_t)q * N_;
    #pragma unroll
    for (int it = 0; it < 2; it++) {
        const int k = (threadIdx.x + it * 256) * 2;
        const int2 ri = *(const int2*)(rel_index + rowi + k);
        const float2 g2 = *(const float2*)(gb + rowi + k);
        const float* t0 = rel_table + ri.x * H_;
        const float* t1 = rel_table + ri.y * H_;
        #pragma unroll
        for (int h = 0; h < H_; h++) {
            const __half2 v = __floats2half2_rn(t0[h] + g2.x, t1[h] + g2.y);
            *(__half2*)(g_biash + (size_t)h * (N_ * N_) + rowi + k) = v;
        }
    }
}

// ---------------- LayerNorm: warp-per-row, shfl-only -------------------------
__global__ __launch_bounds__(256) void ln_kernel(
    const float* __restrict__ in, const float* __restrict__ g,
    const float* __restrict__ bta, __half* __restrict__ out)
{
    const int lane = threadIdx.x & 31;
    const int row  = blockIdx.x * 8 + (threadIdx.x >> 5);
    const float4* xr = (const float4*)(in + (size_t)row * C_);
    const float4 a = xr[lane], b = xr[lane + 32], c = xr[lane + 64];

    float s = (a.x + a.y) + (a.z + a.w) + (b.x + b.y) + (b.z + b.w)
            + (c.x + c.y) + (c.z + c.w);
    #pragma unroll
    for (int o = 16; o; o >>= 1) s += __shfl_xor_sync(0xffffffffu, s, o);
    const float mean = s * (1.0f / C_);

    const float dx[12] = { a.x - mean, a.y - mean, a.z - mean, a.w - mean,
                           b.x - mean, b.y - mean, b.z - mean, b.w - mean,
                           c.x - mean, c.y - mean, c.z - mean, c.w - mean };
    float q = 0.0f;
    #pragma unroll
    for (int i = 0; i < 12; i++) q += dx[i] * dx[i];
    #pragma unroll
    for (int o = 16; o; o >>= 1) q += __shfl_xor_sync(0xffffffffu, q, o);
    const float inv = rsqrtf(q * (1.0f / C_) + 1e-5f);

    const float4* g4 = (const float4*)g;
    const float4* t4 = (const float4*)bta;
    __half* orow = out + (size_t)row * C_;
    #pragma unroll
    for (int seg = 0; seg < 3; seg++) {
        const float4 gv = g4[lane + seg * 32];
        const float4 tv = t4[lane + seg * 32];
        const float* d = &dx[seg * 4];
        __half2 h0 = __floats2half2_rn(d[0] * inv * gv.x + tv.x,
                                       d[1] * inv * gv.y + tv.y);
        __half2 h1 = __floats2half2_rn(d[2] * inv * gv.z + tv.z,
                                       d[3] * inv * gv.w + tv.w);
        uint2 u; u.x = *(uint32_t*)&h0; u.y = *(uint32_t*)&h1;
        *(uint2*)(orow + lane * 4 + seg * 128) = u;
    }
}

// ---------------- fp16 GEMM: 128x128 tile, BK=64, 3-stage cp.async ----------
#define SMS64 72                          // padded row stride (halves)
#define GST (128 * SMS64)                 // per-matrix stage stride
#define GEMM_SMEM (3 * 2 * GST * 2)       // 110592 bytes
template<bool GELU, bool HASB, bool RES, bool OUTH, bool QSC>
__global__ __launch_bounds__(256, 2) void mma_gemm_h(
    const __half* __restrict__ A, const __half* __restrict__ W,
    const float* __restrict__ bias, const float* __restrict__ res,
    void* __restrict__ Cv, int M, int Nd, int K)
{
    extern __shared__ __half dsm[];
    __half* Asb = dsm;                 // 3 stages A
    __half* Bsb = dsm + 3 * GST;       // 3 stages B
    const int tid  = threadIdx.x;
    const int lane = tid & 31, warp = tid >> 5;
    const int wm = warp >> 2, wn = warp & 3;     // 2 x 4, warp tile 64x32
    const int lq = lane >> 2, lr = lane & 3;
    const int bm = blockIdx.y * 128, bn = blockIdx.x * 128;
    const int ntiles = K >> 6;

    const int arow = ((lane >> 3) & 1) * 8 + (lane & 7);
    const int acol = (lane >> 4) * 8;
    const int brow = ((lane >> 4) << 3) + (lane & 7);
    const int bcol = ((lane >> 3) & 1) * 8;

    // loader: 1024 16B-chunks per matrix per stage -> 4 per thread per matrix
    #define ISSUE(kt, buf)                                                       \
    {                                                                            \
        __half* asb = Asb + (buf) * GST;                                         \
        __half* bsb = Bsb + (buf) * GST;                                         \
        _Pragma("unroll")                                                        \
        for (int j = 0; j < 4; j++) {                                            \
            const int cid = tid + j * 256;                                       \
            const int rr = cid >> 3, c8 = (cid & 7) * 8;                         \
            const __half* ag = A + (size_t)(bm + rr) * K + (kt) * 64 + c8;       \
            const __half* wg = W + (size_t)(bn + rr) * K + (kt) * 64 + c8;       \
            uint32_t sa = (uint32_t)__cvta_generic_to_shared(&asb[rr * SMS64 + c8]); \
            uint32_t sb = (uint32_t)__cvta_generic_to_shared(&bsb[rr * SMS64 + c8]); \
            asm volatile("cp.async.cg.shared.global [%0], [%1], 16;" :: "r"(sa), "l"(ag)); \
            asm volatile("cp.async.cg.shared.global [%0], [%1], 16;" :: "r"(sb), "l"(wg)); \
        }                                                                        \
        asm volatile("cp.async.commit_group;");                                  \
    }

    float acc[4][4][4] = {};
    ISSUE(0, 0);
    if (ntiles > 1) ISSUE(1, 1);

    for (int kt = 0; kt < ntiles; kt++) {
        if (kt + 1 < ntiles) asm volatile("cp.async.wait_group 1;");
        else                 asm volatile("cp.async.wait_group 0;");
        __syncthreads();
        if (kt + 2 < ntiles) ISSUE(kt + 2, (kt + 2) % 3);

        const __half* as = Asb + (kt % 3) * GST;
        const __half* bs = Bsb + (kt % 3) * GST;
        #pragma unroll
        for (int ks = 0; ks < 4; ks++) {
            const int c = ks * 16;
            uint32_t af[4][4], bf[4][2];
            #pragma unroll
            for (int mt = 0; mt < 4; mt++)
                ldsm_x4(af[mt], &as[(wm * 64 + mt * 16 + arow) * SMS64 + c + acol]);
            #pragma unroll
            for (int np = 0; np < 2; np++) {
                uint32_t tmp[4];
                ldsm_x4(tmp, &bs[(wn * 32 + np * 16 + brow) * SMS64 + c + bcol]);
                bf[np * 2][0] = tmp[0]; bf[np * 2][1] = tmp[1];
                bf[np * 2 + 1][0] = tmp[2]; bf[np * 2 + 1][1] = tmp[3];
            }
            #pragma unroll
            for (int mt = 0; mt < 4; mt++)
                #pragma unroll
                for (int nt = 0; nt < 4; nt++)
                    mma_f16(acc[mt][nt], af[mt], bf[nt]);
        }
    }
    #undef ISSUE

    #pragma unroll
    for (int mt = 0; mt < 4; mt++) {
        #pragma unroll
        for (int nt = 0; nt < 4; nt++) {
            const int row = bm + wm * 64 + mt * 16 + lq;
            const int col = bn + wn * 32 + nt * 8 + lr * 2;
            #pragma unroll
            for (int half = 0; half < 2; half++) {
                const int r = row + half * 8;
                float v0 = acc[mt][nt][half * 2 + 0];
                float v1 = acc[mt][nt][half * 2 + 1];
                if (HASB) { v0 += bias[col]; v1 += bias[col + 1]; }
                if (GELU) { v0 = gelu_f(v0); v1 = gelu_f(v1); }
                if (RES) {
                    const float* Rr = res + (size_t)r * Nd + col;
                    v0 += Rr[0]; v1 += Rr[1];
                }
                if (OUTH) {
                    if (QSC && col < 384) { v0 *= SCALE_; v1 *= SCALE_; }
                    __half2 hv = __floats2half2_rn(v0, v1);
                    *(__half2*)((__half*)Cv + (size_t)r * Nd + col) = hv;
                } else {
                    *(float2*)((float*)Cv + (size_t)r * Nd + col) = make_float2(v0, v1);
                }
            }
        }
    }
}

// ---------------- depthwise 3x3 dil-2 conv + GELU ---------------------------
__global__ __launch_bounds__(384) void dwconv_kernel(
    const __half* __restrict__ h1, __half* __restrict__ h2,
    const float* __restrict__ w, const float* __restrict__ bias)
{
    const int n = blockIdx.x;
    const int b = blockIdx.y;
    const int y = n >> 5, x = n & 31;
    const size_t base = (size_t)b * N_ * HID_;
    const int c0 = threadIdx.x * 2;

    float2 acc = make_float2(bias[c0], bias[c0 + 1]);
    const float* w0 = w + c0 * 9;
    const float* w1 = w + (c0 + 1) * 9;

    #pragma unroll
    for (int i = 0; i < 3; i++) {
        const int yy = y + 2 * i - 2;
        if (yy < 0 || yy > 31) continue;
        #pragma unroll
        for (int j = 0; j < 3; j++) {
            const int xx = x + 2 * j - 2;
            if (xx < 0 || xx > 31) continue;
            const float2 v = __half22float2(
                *(const __half2*)(h1 + base + (size_t)(yy * 32 + xx) * HID_ + c0));
            acc.x += w0[i * 3 + j] * v.x;
            acc.y += w1[i * 3 + j] * v.y;
        }
    }
    *(__half2*)(h2 + base + (size_t)n * HID_ + c0) =
        __floats2half2_rn(gelu_f(acc.x), gelu_f(acc.y));
}

// ---------------- fp16 flash attention: smem-staged bias --------------------
#define SMSH 40
#define ATT_K(buf)  ((buf) * 64 * SMSH)
#define ATT_V(buf)  (2 * 64 * SMSH + (buf) * 64 * SMSH)
#define ATT_B(buf)  (4 * 64 * SMSH + (buf) * 128 * 72)
#define ATT_SMEM  ((4 * 64 * SMSH + 2 * 128 * 72) * 2)   // 57344 bytes
__global__ __launch_bounds__(256) void attn_mma_kernel(
    const __half* __restrict__ qkv, __half* __restrict__ att)
{
    extern __shared__ __half asm_[];
    const int q0 = blockIdx.x * 128;
    const int h  = blockIdx.y;
    const int b  = blockIdx.z;
    const int tid = threadIdx.x;
    const int lane = tid & 31, w = tid >> 5;
    const int lq = lane >> 2;
    const int lr = lane & 3;

    const size_t qbase = (size_t)b * N_ * 1152;
    const int kl = tid >> 2, d8 = (tid & 3) * 8;
    const __half* bhg = g_biash + (size_t)h * N_ * N_;

    #define AISSUE(kt, buf)                                                      \
    {                                                                            \
        const __half* src = qkv + qbase + (size_t)((kt) * 64 + kl) * 1152 + h * 32 + d8; \
        uint32_t sk = (uint32_t)__cvta_generic_to_shared(&asm_[ATT_K(buf) + kl * SMSH + d8]); \
        uint32_t sv = (uint32_t)__cvta_generic_to_shared(&asm_[ATT_V(buf) + kl * SMSH + d8]); \
        asm volatile("cp.async.cg.shared.global [%0], [%1], 16;" :: "r"(sk), "l"(src + 384)); \
        asm volatile("cp.async.cg.shared.global [%0], [%1], 16;" :: "r"(sv), "l"(src + 768)); \
        _Pragma("unroll")                                                        \
        for (int j = 0; j < 4; j++) {                                            \
            const int cid = tid + j * 256;                                       \
            const int brw = cid >> 3, c8 = cid & 7;                              \
            const __half* bsrc = bhg + (size_t)(q0 + brw) * N_ + (kt) * 64 + c8 * 8; \
            uint32_t bdst = (uint32_t)__cvta_generic_to_shared(                  \
                &asm_[ATT_B(buf) + brw * 72 + c8 * 8]);                          \
            asm volatile("cp.async.cg.shared.global [%0], [%1], 16;" :: "r"(bdst), "l"(bsrc)); \
        }                                                                        \
        asm volatile("cp.async.commit_group;");                                  \
    }

    const int brow = ((lane >> 4) << 3) + (lane & 7);
    const int bcol = ((lane >> 3) & 1) * 8;

    uint32_t qa[2][4];
    const int br0 = q0 + w * 16 + lq;
    {
        const __half* qp  = qkv + qbase + (size_t)br0 * 1152 + h * 32;
        const __half* qp8 = qp + 8 * 1152;
        #pragma unroll
        for (int ks = 0; ks < 2; ks++) {
            const int c = ks * 16 + 2 * lr;
            qa[ks][0] = *(const uint32_t*)(qp  + c);
            qa[ks][1] = *(const uint32_t*)(qp8 + c);
            qa[ks][2] = *(const uint32_t*)(qp  + c + 8);
            qa[ks][3] = *(const uint32_t*)(qp8 + c + 8);
        }
    }

    float o[4][4] = {};
    float m0 = -1e30f, m1 = -1e30f, l0 = 0.0f, l1 = 0.0f;

    AISSUE(0, 0);
    for (int kt = 0; kt < 16; kt++) {
        asm volatile("cp.async.wait_group 0;");
        __syncthreads();
        if (kt < 15) AISSUE(kt + 1, (kt + 1) & 1);

        const int buf = kt & 1;

        float s[8][4];
        #pragma unroll
        for (int nf = 0; nf < 8; nf++)
            s[nf][0] = s[nf][1] = s[nf][2] = s[nf][3] = 0.0f;
        #pragma unroll
        for (int ks = 0; ks < 2; ks++) {
            const int c = ks * 16;
            uint32_t kf[8][2];
            #pragma unroll
            for (int np = 0; np < 4; np++) {
                uint32_t tmp[4];
                ldsm_x4(tmp, &asm_[ATT_K(buf) + (np * 16 + brow) * SMSH + c + bcol]);
                kf[np * 2][0] = tmp[0]; kf[np * 2][1] = tmp[1];
                kf[np * 2 + 1][0] = tmp[2]; kf[np * 2 + 1][1] = tmp[3];
            }
            #pragma unroll
            for (int nf = 0; nf < 8; nf++)
                mma_f16(s[nf], qa[ks], kf[nf]);
        }

        const __half* bs0 = &asm_[ATT_B(buf) + (w * 16 + lq) * 72];
        const __half* bs1 = bs0 + 8 * 72;
        float nm0 = m0, nm1 = m1;
        #pragma unroll
        for (int nf = 0; nf < 8; nf++) {
            const int col = nf * 8 + lr * 2;
            const float2 b0v = __half22float2(*(const __half2*)(bs0 + col));
            const float2 b1v = __half22float2(*(const __half2*)(bs1 + col));
            s[nf][0] += b0v.x; s[nf][1] += b0v.y;
            s[nf][2] += b1v.x; s[nf][3] += b1v.y;
            nm0 = fmaxf(nm0, fmaxf(s[nf][0], s[nf][1]));
            nm1 = fmaxf(nm1, fmaxf(s[nf][2], s[nf][3]));
        }
        nm0 = fmaxf(nm0, __shfl_xor_sync(0xffffffffu, nm0, 1));
        nm0 = fmaxf(nm0, __shfl_xor_sync(0xffffffffu, nm0, 2));
        nm1 = fmaxf(nm1, __shfl_xor_sync(0xffffffffu, nm1, 1));
        nm1 = fmaxf(nm1, __shfl_xor_sync(0xffffffffu, nm1, 2));

        const float c0 = __expf(m0 - nm0), c1 = __expf(m1 - nm1);
        m0 = nm0; m1 = nm1; l0 *= c0; l1 *= c1;
        #pragma unroll
        for (int nf = 0; nf < 4; nf++) {
            o[nf][0] *= c0; o[nf][1] *= c0;
            o[nf][2] *= c1; o[nf][3] *= c1;
        }

        uint32_t ph[8][2];
        float a0 = 0.0f, a1 = 0.0f;
        #pragma unroll
        for (int nf = 0; nf < 8; nf++) {
            const __half2 x01 = __floats2half2_rn((s[nf][0] - nm0) * LOG2E_,
                                                  (s[nf][1] - nm0) * LOG2E_);
            const __half2 x23 = __floats2half2_rn((s[nf][2] - nm1) * LOG2E_,
                                                  (s[nf][3] - nm1) * LOG2E_);
            const __half2 p01 = h2exp2(x01);
            const __half2 p23 = h2exp2(x23);
            const float2 f01 = __half22float2(p01);
            const float2 f23 = __half22float2(p23);
            a0 += f01.x + f01.y;
            a1 += f23.x + f23.y;
            ph[nf][0] = *(const uint32_t*)&p01;
            ph[nf][1] = *(const uint32_t*)&p23;
        }
        a0 += __shfl_xor_sync(0xffffffffu, a0, 1);
        a0 += __shfl_xor_sync(0xffffffffu, a0, 2);
        a1 += __shfl_xor_sync(0xffffffffu, a1, 1);
        a1 += __shfl_xor_sync(0xffffffffu, a1, 2);
        l0 += a0; l1 += a1;

        #pragma unroll
        for (int kf2 = 0; kf2 < 4; kf2++) {
            uint32_t pa[4];
            pa[0] = ph[2 * kf2][0];
            pa[1] = ph[2 * kf2][1];
            pa[2] = ph[2 * kf2 + 1][0];
            pa[3] = ph[2 * kf2 + 1][1];
            #pragma unroll
            for (int nf = 0; nf < 4; nf++) {
                uint32_t b0r, b1r;
                ldsm_x2_t(b0r, b1r,
                          &asm_[ATT_V(buf) + (kf2 * 16 + (lane & 15)) * SMSH + nf * 8]);
                uint32_t bfr[2] = { b0r, b1r };
                mma_f16(o[nf], pa, bfr);
            }
        }
    }
    #undef AISSUE

    const float inv0 = 1.0f / l0, inv1 = 1.0f / l1;
    #pragma unroll
    for (int nf = 0; nf < 4; nf++) {
        const int col = h * 32 + nf * 8 + lr * 2;
        __half* o0 = att + ((size_t)b * N_ + br0) * C_ + col;
        __half* o1 = att + ((size_t)b * N_ + br0 + 8) * C_ + col;
        *(__half2*)o0 = __floats2half2_rn(o[nf][0] * inv0, o[nf][1] * inv0);
        *(__half2*)o1 = __floats2half2_rn(o[nf][2] * inv1, o[nf][3] * inv1);
    }
}

// ---------------- launch ----------------
extern "C" void kernel_launch(void* const* d_in, const int* in_sizes, int n_in,
                              void* d_out, int out_size)
{
    const int base = (n_in >= 19) ? 2 : 0;
    const float* x         = (const float*)d_in[0];
    const int*   rel_index = (const int*)  d_in[1 + base];
    const float* ln1_g     = (const float*)d_in[2 + base];
    const float* ln1_b     = (const float*)d_in[3 + base];
    const float* w_qkv     = (const float*)d_in[4 + base];
    const float* w_proj    = (const float*)d_in[5 + base];
    const float* b_proj    = (const float*)d_in[6 + base];
    const float* rel_table = (const float*)d_in[7 + base];
    const float* gbias     = (const float*)d_in[8 + base];
    const float* ln2_g     = (const float*)d_in[9 + base];
    const float* ln2_b     = (const float*)d_in[10 + base];
    const float* w_pw1     = (const float*)d_in[11 + base];
    const float* b_pw1     = (const float*)d_in[12 + base];
    const float* w_dw      = (const float*)d_in[13 + base];
    const float* b_dw      = (const float*)d_in[14 + base];
    const float* w_pw2     = (const float*)d_in[15 + base];
    const float* b_pw2     = (const float*)d_in[16 + base];
    float* out = (float*)d_out;

    void *p_ln2, *p_h1, *p_h2, *p_x1, *p_ln1, *p_qkvh, *p_atth, *p_wh;
    cudaGetSymbolAddress(&p_ln2, g_ln2);
    cudaGetSymbolAddress(&p_h1,  g_h1);
    cudaGetSymbolAddress(&p_h2,  g_h2);
    cudaGetSymbolAddress(&p_x1,  g_x1);
    cudaGetSymbolAddress(&p_ln1, g_ln1);
    cudaGetSymbolAddress(&p_qkvh, g_qkvh);
    cudaGetSymbolAddress(&p_atth, g_atth);
    cudaGetSymbolAddress(&p_wh,  g_wh);
    __half* wh = (__half*)p_wh;

    static bool attr_done = false;
    if (!attr_done) {
        cudaFuncSetAttribute(mma_gemm_h<true, true, false, true, false>,
                             cudaFuncAttributeMaxDynamicSharedMemorySize, GEMM_SMEM);
        cudaFuncSetAttribute(mma_gemm_h<false, true, true, false, false>,
                             cudaFuncAttributeMaxDynamicSharedMemorySize, GEMM_SMEM);
        cudaFuncSetAttribute(mma_gemm_h<false, false, false, true, true>,
                             cudaFuncAttributeMaxDynamicSharedMemorySize, GEMM_SMEM);
        cudaFuncSetAttribute(attn_mma_kernel,
                             cudaFuncAttributeMaxDynamicSharedMemorySize, ATT_SMEM);
        attr_done = true;
    }

    prep_kernel<<<PREP_W2H_BLOCKS + N_, 256>>>(
        w_qkv, w_pw1, w_pw2, w_proj, wh, rel_index, rel_table, gbias);

    // 1) x1 = x + MLP(LN2(x))
    ln_kernel<<<M_ / 8, 256>>>(x, ln2_g, ln2_b, (__half*)p_ln2);
    mma_gemm_h<true, true, false, true, false><<<dim3(HID_ / 128, M_ / 128), 256, GEMM_SMEM>>>(
        (const __half*)p_ln2, wh + OFF_PW1, b_pw1, nullptr, p_h1, M_, HID_, C_);
    dwconv_kernel<<<dim3(N_, B_), 384>>>(
        (const __half*)p_h1, (__half*)p_h2, w_dw, b_dw);
    mma_gemm_h<false, true, true, false, false><<<dim3(C_ / 128, M_ / 128), 256, GEMM_SMEM>>>(
        (const __half*)p_h2, wh + OFF_PW2, b_pw2, x, p_x1, M_, C_, HID_);

    // 2) out = x1 + Attn(LN1(x1))
    ln_kernel<<<M_ / 8, 256>>>((const float*)p_x1, ln1_g, ln1_b, (__half*)p_ln1);
    mma_gemm_h<false, false, false, true, true><<<dim3(1152 / 128, M_ / 128), 256, GEMM_SMEM>>>(
        (const __half*)p_ln1, wh + OFF_QKV, nullptr, nullptr, p_qkvh, M_, 1152, C_);
    attn_mma_kernel<<<dim3(N_ / 128, H_, B_), 256, ATT_SMEM>>>(
        (const __half*)p_qkvh, (__half*)p_atth);
    mma_gemm_h<false, true, true, false, false><<<dim3(C_ / 128, M_ / 128), 256, GEMM_SMEM>>>(
        (const __half*)p_atth, wh + OFF_PROJ, b_proj, (const float*)p_x1, out, M_, C_, C_);
}

// round 17
// speedup vs baseline: 1.0758x; 1.0470x over previous
#include <cuda_runtime.h>
#include <cuda_fp16.h>
#include <math.h>
#include <stdint.h>

// Problem constants
#define B_  8
#define N_  1024
#define C_  384
#define H_  12
#define HD_ 32
#define HID_ 768
#define M_  (B_ * N_)
#define NREL_ 3969
#define SCALE_ 0.17677669529663687f
#define LOG2E_ 1.4426950408889634f

// NOTE: harness PTX target is sm_103 (no 'a') -> tcgen05.* unavailable.
// GEMMs are HMMA-issue-bound (~150 TF/s floor on mma.sync path).

__device__ __forceinline__ float gelu_f(float v) {
    return 0.5f * v * (1.0f + erff(v * 0.70710678118654752f));
}

__device__ __forceinline__ void mma_f16(float* c, const uint32_t* a, const uint32_t* b) {
    asm volatile(
        "mma.sync.aligned.m16n8k16.row.col.f32.f16.f16.f32 "
        "{%0,%1,%2,%3}, {%4,%5,%6,%7}, {%8,%9}, {%0,%1,%2,%3};"
        : "+f"(c[0]), "+f"(c[1]), "+f"(c[2]), "+f"(c[3])
        : "r"(a[0]), "r"(a[1]), "r"(a[2]), "r"(a[3]), "r"(b[0]), "r"(b[1]));
}

__device__ __forceinline__ void ldsm_x4(uint32_t* r, const __half* p) {
    uint32_t addr = (uint32_t)__cvta_generic_to_shared(p);
    asm volatile("ldmatrix.sync.aligned.m8n8.x4.shared.b16 {%0,%1,%2,%3}, [%4];"
                 : "=r"(r[0]), "=r"(r[1]), "=r"(r[2]), "=r"(r[3]) : "r"(addr));
}

__device__ __forceinline__ void ldsm_x2_t(uint32_t& r0, uint32_t& r1, const __half* p) {
    uint32_t addr = (uint32_t)__cvta_generic_to_shared(p);
    asm volatile("ldmatrix.sync.aligned.m8n8.x2.trans.shared.b16 {%0,%1}, [%2];"
                 : "=r"(r0), "=r"(r1) : "r"(addr));
}

// ---------------- scratch ----------------
__device__ __align__(16) __half g_ln2[M_ * C_];
__device__ __align__(16) __half g_h1 [M_ * HID_];
__device__ __align__(16) __half g_h2 [M_ * HID_];
__device__ float g_x1 [M_ * C_];
__device__ __align__(16) __half g_ln1[M_ * C_];
__device__ __align__(16) __half g_qkvh[M_ * 3 * C_];
__device__ __align__(16) __half g_atth[M_ * C_];
__device__ __align__(16) __half g_biash[H_ * N_ * N_];
__device__ __align__(16) __half g_wh[1179648];
#define OFF_QKV  0
#define OFF_PW1  442368
#define OFF_PW2  737280
#define OFF_PROJ 1032192
#define Q_QKV  110592
#define Q_PW1  184320
#define Q_PW2  258048
#define Q_END  294912
#define PREP_W2H_BLOCKS ((Q_END + 255) / 256)   // 1152

// ---------------- merged prep: weight f32->f16 + bias precompute ------------
__global__ __launch_bounds__(256) void prep_kernel(
    const float* __restrict__ s_qkv, const float* __restrict__ s_pw1,
    const float* __restrict__ s_pw2, const float* __restrict__ s_proj,
    __half* __restrict__ dst,
    const int* __restrict__ rel_index, const float* __restrict__ rel_table,
    const float* __restrict__ gb)
{
    if (blockIdx.x < PREP_W2H_BLOCKS) {
        const int i = blockIdx.x * 256 + threadIdx.x;
        if (i >= Q_END) return;
        const float* src; int local;
        if (i < Q_QKV)      { src = s_qkv;  local = i; }
        else if (i < Q_PW1) { src = s_pw1;  local = i - Q_QKV; }
        else if (i < Q_PW2) { src = s_pw2;  local = i - Q_PW1; }
        else                { src = s_proj; local = i - Q_PW2; }
        const float4 v = ((const float4*)src)[local];
        __half2 h0 = __floats2half2_rn(v.x, v.y);
        __half2 h1 = __floats2half2_rn(v.z, v.w);
        uint2 u; u.x = *(uint32_t*)&h0; u.y = *(uint32_t*)&h1;
        *(uint2*)(dst + (size_t)i * 4) = u;
        return;
    }
    const int q = blockIdx.x - PREP_W2H_BLOCKS;
    const size_t rowi = (size_t)q * N_;
    #pragma unroll
    for (int it = 0; it < 2; it++) {
        const int k = (threadIdx.x + it * 256) * 2;
        const int2 ri = *(const int2*)(rel_index + rowi + k);
        const float2 g2 = *(const float2*)(gb + rowi + k);
        const float* t0 = rel_table + ri.x * H_;
        const float* t1 = rel_table + ri.y * H_;
        #pragma unroll
        for (int h = 0; h < H_; h++) {
            const __half2 v = __floats2half2_rn(t0[h] + g2.x, t1[h] + g2.y);
            *(__half2*)(g_biash + (size_t)h * (N_ * N_) + rowi + k) = v;
        }
    }
}

// ---------------- LayerNorm: warp-per-row, shfl-only -------------------------
__global__ __launch_bounds__(256) void ln_kernel(
    const float* __restrict__ in, const float* __restrict__ g,
    const float* __restrict__ bta, __half* __restrict__ out)
{
    const int lane = threadIdx.x & 31;
    const int row  = blockIdx.x * 8 + (threadIdx.x >> 5);
    const float4* xr = (const float4*)(in + (size_t)row * C_);
    const float4 a = xr[lane], b = xr[lane + 32], c = xr[lane + 64];

    float s = (a.x + a.y) + (a.z + a.w) + (b.x + b.y) + (b.z + b.w)
            + (c.x + c.y) + (c.z + c.w);
    #pragma unroll
    for (int o = 16; o; o >>= 1) s += __shfl_xor_sync(0xffffffffu, s, o);
    const float mean = s * (1.0f / C_);

    const float dx[12] = { a.x - mean, a.y - mean, a.z - mean, a.w - mean,
                           b.x - mean, b.y - mean, b.z - mean, b.w - mean,
                           c.x - mean, c.y - mean, c.z - mean, c.w - mean };
    float q = 0.0f;
    #pragma unroll
    for (int i = 0; i < 12; i++) q += dx[i] * dx[i];
    #pragma unroll
    for (int o = 16; o; o >>= 1) q += __shfl_xor_sync(0xffffffffu, q, o);
    const float inv = rsqrtf(q * (1.0f / C_) + 1e-5f);

    const float4* g4 = (const float4*)g;
    const float4* t4 = (const float4*)bta;
    __half* orow = out + (size_t)row * C_;
    #pragma unroll
    for (int seg = 0; seg < 3; seg++) {
        const float4 gv = g4[lane + seg * 32];
        const float4 tv = t4[lane + seg * 32];
        const float* d = &dx[seg * 4];
        __half2 h0 = __floats2half2_rn(d[0] * inv * gv.x + tv.x,
                                       d[1] * inv * gv.y + tv.y);
        __half2 h1 = __floats2half2_rn(d[2] * inv * gv.z + tv.z,
                                       d[3] * inv * gv.w + tv.w);
        uint2 u; u.x = *(uint32_t*)&h0; u.y = *(uint32_t*)&h1;
        *(uint2*)(orow + lane * 4 + seg * 128) = u;
    }
}

// ---------------- fp16 GEMM: 128x128 tile, BK=64, 3-stage cp.async ----------
#define SMS64 72
#define GST (128 * SMS64)
#define GEMM_SMEM (3 * 2 * GST * 2)       // 110592 bytes
template<bool GELU, bool HASB, bool RES, bool OUTH, bool QSC>
__global__ __launch_bounds__(256, 2) void mma_gemm_h(
    const __half* __restrict__ A, const __half* __restrict__ W,
    const float* __restrict__ bias, const float* __restrict__ res,
    void* __restrict__ Cv, int M, int Nd, int K)
{
    extern __shared__ __half dsm[];
    __half* Asb = dsm;
    __half* Bsb = dsm + 3 * GST;
    const int tid  = threadIdx.x;
    const int lane = tid & 31, warp = tid >> 5;
    const int wm = warp >> 2, wn = warp & 3;
    const int lq = lane >> 2, lr = lane & 3;
    const int bm = blockIdx.y * 128, bn = blockIdx.x * 128;
    const int ntiles = K >> 6;

    const int arow = ((lane >> 3) & 1) * 8 + (lane & 7);
    const int acol = (lane >> 4) * 8;
    const int brow = ((lane >> 4) << 3) + (lane & 7);
    const int bcol = ((lane >> 3) & 1) * 8;

    #define ISSUE(kt, buf)                                                       \
    {                                                                            \
        __half* asb = Asb + (buf) * GST;                                         \
        __half* bsb = Bsb + (buf) * GST;                                         \
        _Pragma("unroll")                                                        \
        for (int j = 0; j < 4; j++) {                                            \
            const int cid = tid + j * 256;                                       \
            const int rr = cid >> 3, c8 = (cid & 7) * 8;                         \
            const __half* ag = A + (size_t)(bm + rr) * K + (kt) * 64 + c8;       \
            const __half* wg = W + (size_t)(bn + rr) * K + (kt) * 64 + c8;       \
            uint32_t sa = (uint32_t)__cvta_generic_to_shared(&asb[rr * SMS64 + c8]); \
            uint32_t sb = (uint32_t)__cvta_generic_to_shared(&bsb[rr * SMS64 + c8]); \
            asm volatile("cp.async.cg.shared.global [%0], [%1], 16;" :: "r"(sa), "l"(ag)); \
            asm volatile("cp.async.cg.shared.global [%0], [%1], 16;" :: "r"(sb), "l"(wg)); \
        }                                                                        \
        asm volatile("cp.async.commit_group;");                                  \
    }

    float acc[4][4][4] = {};
    ISSUE(0, 0);
    if (ntiles > 1) ISSUE(1, 1);

    for (int kt = 0; kt < ntiles; kt++) {
        if (kt + 1 < ntiles) asm volatile("cp.async.wait_group 1;");
        else                 asm volatile("cp.async.wait_group 0;");
        __syncthreads();
        if (kt + 2 < ntiles) ISSUE(kt + 2, (kt + 2) % 3);

        const __half* as = Asb + (kt % 3) * GST;
        const __half* bs = Bsb + (kt % 3) * GST;
        #pragma unroll
        for (int ks = 0; ks < 4; ks++) {
            const int c = ks * 16;
            uint32_t af[4][4], bf[4][2];
            #pragma unroll
            for (int mt = 0; mt < 4; mt++)
                ldsm_x4(af[mt], &as[(wm * 64 + mt * 16 + arow) * SMS64 + c + acol]);
            #pragma unroll
            for (int np = 0; np < 2; np++) {
                uint32_t tmp[4];
                ldsm_x4(tmp, &bs[(wn * 32 + np * 16 + brow) * SMS64 + c + bcol]);
                bf[np * 2][0] = tmp[0]; bf[np * 2][1] = tmp[1];
                bf[np * 2 + 1][0] = tmp[2]; bf[np * 2 + 1][1] = tmp[3];
            }
            #pragma unroll
            for (int mt = 0; mt < 4; mt++)
                #pragma unroll
                for (int nt = 0; nt < 4; nt++)
                    mma_f16(acc[mt][nt], af[mt], bf[nt]);
        }
    }
    #undef ISSUE

    #pragma unroll
    for (int mt = 0; mt < 4; mt++) {
        #pragma unroll
        for (int nt = 0; nt < 4; nt++) {
            const int row = bm + wm * 64 + mt * 16 + lq;
            const int col = bn + wn * 32 + nt * 8 + lr * 2;
            #pragma unroll
            for (int half = 0; half < 2; half++) {
                const int r = row + half * 8;
                float v0 = acc[mt][nt][half * 2 + 0];
                float v1 = acc[mt][nt][half * 2 + 1];
                if (HASB) { v0 += bias[col]; v1 += bias[col + 1]; }
                if (GELU) { v0 = gelu_f(v0); v1 = gelu_f(v1); }
                if (RES) {
                    const float* Rr = res + (size_t)r * Nd + col;
                    v0 += Rr[0]; v1 += Rr[1];
                }
                if (OUTH) {
                    if (QSC && col < 384) { v0 *= SCALE_; v1 *= SCALE_; }
                    __half2 hv = __floats2half2_rn(v0, v1);
                    *(__half2*)((__half*)Cv + (size_t)r * Nd + col) = hv;
                } else {
                    *(float2*)((float*)Cv + (size_t)r * Nd + col) = make_float2(v0, v1);
                }
            }
        }
    }
}

// ---------------- dwconv: row sweep with sliding 3x3 register window --------
// grid (32, B_, 2): one block per (row, batch, column parity). Thread owns 2
// channels, sweeps 16 pixels. 3 new half2 loads/pixel; weights in registers.
// Boundary taps are exact zeros (FMA with 0 == identity) -> bit-identical.
__global__ __launch_bounds__(384) void dwconv_kernel(
    const __half* __restrict__ h1, __half* __restrict__ h2,
    const float* __restrict__ w, const float* __restrict__ bias)
{
    const int y = blockIdx.x;
    const int b = blockIdx.y;
    const int p = blockIdx.z;            // column parity
    const size_t base = (size_t)b * N_ * HID_;
    const int c0 = threadIdx.x * 2;

    float wa[9], wb[9];
    #pragma unroll
    for (int t = 0; t < 9; t++) {
        wa[t] = w[c0 * 9 + t];
        wb[t] = w[(c0 + 1) * 9 + t];
    }
    const float ba = bias[c0], bb = bias[c0 + 1];

    const __half* rp[3];
    bool vy[3];
    #pragma unroll
    for (int i = 0; i < 3; i++) {
        const int yy = y + 2 * i - 2;
        vy[i] = (yy >= 0) && (yy <= 31);
        rp[i] = h1 + base + (size_t)(yy * 32) * HID_ + c0;
    }

    float2 win[3][3];   // [row][slot]: slot 0 = x-2, 1 = x, 2 = x+2
    #pragma unroll
    for (int i = 0; i < 3; i++) {
        win[i][0] = make_float2(0.0f, 0.0f);   // x-2 < 0 at x = p
        win[i][1] = vy[i] ? __half22float2(*(const __half2*)(rp[i] + (size_t)p * HID_))
                          : make_float2(0.0f, 0.0f);
        win[i][2] = vy[i] ? __half22float2(*(const __half2*)(rp[i] + (size_t)(p + 2) * HID_))
                          : make_float2(0.0f, 0.0f);
    }

    __half* orow = h2 + base + (size_t)(y * 32) * HID_ + c0;
    for (int x = p; x < 32; x += 2) {
        float va = ba, vb = bb;
        #pragma unroll
        for (int i = 0; i < 3; i++)
            #pragma unroll
            for (int j = 0; j < 3; j++) {
                va += wa[i * 3 + j] * win[i][j].x;
                vb += wb[i * 3 + j] * win[i][j].y;
            }
        *(__half2*)(orow + (size_t)x * HID_) =
            __floats2half2_rn(gelu_f(va), gelu_f(vb));

        const int xn = x + 4;
        #pragma unroll
        for (int i = 0; i < 3; i++) {
            win[i][0] = win[i][1];
            win[i][1] = win[i][2];
            win[i][2] = (vy[i] && xn < 32)
                ? __half22float2(*(const __half2*)(rp[i] + (size_t)xn * HID_))
                : make_float2(0.0f, 0.0f);
        }
    }
}

// ---------------- fp16 flash attention: smem-staged bias --------------------
#define SMSH 40
#define ATT_K(buf)  ((buf) * 64 * SMSH)
#define ATT_V(buf)  (2 * 64 * SMSH + (buf) * 64 * SMSH)
#define ATT_B(buf)  (4 * 64 * SMSH + (buf) * 128 * 72)
#define ATT_SMEM  ((4 * 64 * SMSH + 2 * 128 * 72) * 2)   // 57344 bytes
__global__ __launch_bounds__(256) void attn_mma_kernel(
    const __half* __restrict__ qkv, __half* __restrict__ att)
{
    extern __shared__ __half asm_[];
    const int q0 = blockIdx.x * 128;
    const int h  = blockIdx.y;
    const int b  = blockIdx.z;
    const int tid = threadIdx.x;
    const int lane = tid & 31, w = tid >> 5;
    const int lq = lane >> 2;
    const int lr = lane & 3;

    const size_t qbase = (size_t)b * N_ * 1152;
    const int kl = tid >> 2, d8 = (tid & 3) * 8;
    const __half* bhg = g_biash + (size_t)h * N_ * N_;

    #define AISSUE(kt, buf)                                                      \
    {                                                                            \
        const __half* src = qkv + qbase + (size_t)((kt) * 64 + kl) * 1152 + h * 32 + d8; \
        uint32_t sk = (uint32_t)__cvta_generic_to_shared(&asm_[ATT_K(buf) + kl * SMSH + d8]); \
        uint32_t sv = (uint32_t)__cvta_generic_to_shared(&asm_[ATT_V(buf) + kl * SMSH + d8]); \
        asm volatile("cp.async.cg.shared.global [%0], [%1], 16;" :: "r"(sk), "l"(src + 384)); \
        asm volatile("cp.async.cg.shared.global [%0], [%1], 16;" :: "r"(sv), "l"(src + 768)); \
        _Pragma("unroll")                                                        \
        for (int j = 0; j < 4; j++) {                                            \
            const int cid = tid + j * 256;                                       \
            const int brw = cid >> 3, c8 = cid & 7;                              \
            const __half* bsrc = bhg + (size_t)(q0 + brw) * N_ + (kt) * 64 + c8 * 8; \
            uint32_t bdst = (uint32_t)__cvta_generic_to_shared(                  \
                &asm_[ATT_B(buf) + brw * 72 + c8 * 8]);                          \
            asm volatile("cp.async.cg.shared.global [%0], [%1], 16;" :: "r"(bdst), "l"(bsrc)); \
        }                                                                        \
        asm volatile("cp.async.commit_group;");                                  \
    }

    const int brow = ((lane >> 4) << 3) + (lane & 7);
    const int bcol = ((lane >> 3) & 1) * 8;

    uint32_t qa[2][4];
    const int br0 = q0 + w * 16 + lq;
    {
        const __half* qp  = qkv + qbase + (size_t)br0 * 1152 + h * 32;
        const __half* qp8 = qp + 8 * 1152;
        #pragma unroll
        for (int ks = 0; ks < 2; ks++) {
            const int c = ks * 16 + 2 * lr;
            qa[ks][0] = *(const uint32_t*)(qp  + c);
            qa[ks][1] = *(const uint32_t*)(qp8 + c);
            qa[ks][2] = *(const uint32_t*)(qp  + c + 8);
            qa[ks][3] = *(const uint32_t*)(qp8 + c + 8);
        }
    }

    float o[4][4] = {};
    float m0 = -1e30f, m1 = -1e30f, l0 = 0.0f, l1 = 0.0f;

    AISSUE(0, 0);
    for (int kt = 0; kt < 16; kt++) {
        asm volatile("cp.async.wait_group 0;");
        __syncthreads();
        if (kt < 15) AISSUE(kt + 1, (kt + 1) & 1);

        const int buf = kt & 1;

        float s[8][4];
        #pragma unroll
        for (int nf = 0; nf < 8; nf++)
            s[nf][0] = s[nf][1] = s[nf][2] = s[nf][3] = 0.0f;
        #pragma unroll
        for (int ks = 0; ks < 2; ks++) {
            const int c = ks * 16;
            uint32_t kf[8][2];
            #pragma unroll
            for (int np = 0; np < 4; np++) {
                uint32_t tmp[4];
                ldsm_x4(tmp, &asm_[ATT_K(buf) + (np * 16 + brow) * SMSH + c + bcol]);
                kf[np * 2][0] = tmp[0]; kf[np * 2][1] = tmp[1];
                kf[np * 2 + 1][0] = tmp[2]; kf[np * 2 + 1][1] = tmp[3];
            }
            #pragma unroll
            for (int nf = 0; nf < 8; nf++)
                mma_f16(s[nf], qa[ks], kf[nf]);
        }

        const __half* bs0 = &asm_[ATT_B(buf) + (w * 16 + lq) * 72];
        const __half* bs1 = bs0 + 8 * 72;
        float nm0 = m0, nm1 = m1;
        #pragma unroll
        for (int nf = 0; nf < 8; nf++) {
            const int col = nf * 8 + lr * 2;
            const float2 b0v = __half22float2(*(const __half2*)(bs0 + col));
            const float2 b1v = __half22float2(*(const __half2*)(bs1 + col));
            s[nf][0] += b0v.x; s[nf][1] += b0v.y;
            s[nf][2] += b1v.x; s[nf][3] += b1v.y;
            nm0 = fmaxf(nm0, fmaxf(s[nf][0], s[nf][1]));
            nm1 = fmaxf(nm1, fmaxf(s[nf][2], s[nf][3]));
        }
        nm0 = fmaxf(nm0, __shfl_xor_sync(0xffffffffu, nm0, 1));
        nm0 = fmaxf(nm0, __shfl_xor_sync(0xffffffffu, nm0, 2));
        nm1 = fmaxf(nm1, __shfl_xor_sync(0xffffffffu, nm1, 1));
        nm1 = fmaxf(nm1, __shfl_xor_sync(0xffffffffu, nm1, 2));

        const float c0 = __expf(m0 - nm0), c1 = __expf(m1 - nm1);
        m0 = nm0; m1 = nm1; l0 *= c0; l1 *= c1;
        #pragma unroll
        for (int nf = 0; nf < 4; nf++) {
            o[nf][0] *= c0; o[nf][1] *= c0;
            o[nf][2] *= c1; o[nf][3] *= c1;
        }

        uint32_t ph[8][2];
        float a0 = 0.0f, a1 = 0.0f;
        #pragma unroll
        for (int nf = 0; nf < 8; nf++) {
            const __half2 x01 = __floats2half2_rn((s[nf][0] - nm0) * LOG2E_,
                                                  (s[nf][1] - nm0) * LOG2E_);
            const __half2 x23 = __floats2half2_rn((s[nf][2] - nm1) * LOG2E_,
                                                  (s[nf][3] - nm1) * LOG2E_);
            const __half2 p01 = h2exp2(x01);
            const __half2 p23 = h2exp2(x23);
            const float2 f01 = __half22float2(p01);
            const float2 f23 = __half22float2(p23);
            a0 += f01.x + f01.y;
            a1 += f23.x + f23.y;
            ph[nf][0] = *(const uint32_t*)&p01;
            ph[nf][1] = *(const uint32_t*)&p23;
        }
        a0 += __shfl_xor_sync(0xffffffffu, a0, 1);
        a0 += __shfl_xor_sync(0xffffffffu, a0, 2);
        a1 += __shfl_xor_sync(0xffffffffu, a1, 1);
        a1 += __shfl_xor_sync(0xffffffffu, a1, 2);
        l0 += a0; l1 += a1;

        #pragma unroll
        for (int kf2 = 0; kf2 < 4; kf2++) {
            uint32_t pa[4];
            pa[0] = ph[2 * kf2][0];
            pa[1] = ph[2 * kf2][1];
            pa[2] = ph[2 * kf2 + 1][0];
            pa[3] = ph[2 * kf2 + 1][1];
            #pragma unroll
            for (int nf = 0; nf < 4; nf++) {
                uint32_t b0r, b1r;
                ldsm_x2_t(b0r, b1r,
                          &asm_[ATT_V(buf) + (kf2 * 16 + (lane & 15)) * SMSH + nf * 8]);
                uint32_t bfr[2] = { b0r, b1r };
                mma_f16(o[nf], pa, bfr);
            }
        }
    }
    #undef AISSUE

    const float inv0 = 1.0f / l0, inv1 = 1.0f / l1;
    #pragma unroll
    for (int nf = 0; nf < 4; nf++) {
        const int col = h * 32 + nf * 8 + lr * 2;
        __half* o0 = att + ((size_t)b * N_ + br0) * C_ + col;
        __half* o1 = att + ((size_t)b * N_ + br0 + 8) * C_ + col;
        *(__half2*)o0 = __floats2half2_rn(o[nf][0] * inv0, o[nf][1] * inv0);
        *(__half2*)o1 = __floats2half2_rn(o[nf][2] * inv1, o[nf][3] * inv1);
    }
}

// ---------------- launch ----------------
extern "C" void kernel_launch(void* const* d_in, const int* in_sizes, int n_in,
                              void* d_out, int out_size)
{
    const int base = (n_in >= 19) ? 2 : 0;
    const float* x         = (const float*)d_in[0];
    const int*   rel_index = (const int*)  d_in[1 + base];
    const float* ln1_g     = (const float*)d_in[2 + base];
    const float* ln1_b     = (const float*)d_in[3 + base];
    const float* w_qkv     = (const float*)d_in[4 + base];
    const float* w_proj    = (const float*)d_in[5 + base];
    const float* b_proj    = (const float*)d_in[6 + base];
    const float* rel_table = (const float*)d_in[7 + base];
    const float* gbias     = (const float*)d_in[8 + base];
    const float* ln2_g     = (const float*)d_in[9 + base];
    const float* ln2_b     = (const float*)d_in[10 + base];
    const float* w_pw1     = (const float*)d_in[11 + base];
    const float* b_pw1     = (const float*)d_in[12 + base];
    const float* w_dw      = (const float*)d_in[13 + base];
    const float* b_dw      = (const float*)d_in[14 + base];
    const float* w_pw2     = (const float*)d_in[15 + base];
    const float* b_pw2     = (const float*)d_in[16 + base];
    float* out = (float*)d_out;

    void *p_ln2, *p_h1, *p_h2, *p_x1, *p_ln1, *p_qkvh, *p_atth, *p_wh;
    cudaGetSymbolAddress(&p_ln2, g_ln2);
    cudaGetSymbolAddress(&p_h1,  g_h1);
    cudaGetSymbolAddress(&p_h2,  g_h2);
    cudaGetSymbolAddress(&p_x1,  g_x1);
    cudaGetSymbolAddress(&p_ln1, g_ln1);
    cudaGetSymbolAddress(&p_qkvh, g_qkvh);
    cudaGetSymbolAddress(&p_atth, g_atth);
    cudaGetSymbolAddress(&p_wh,  g_wh);
    __half* wh = (__half*)p_wh;

    static bool attr_done = false;
    if (!attr_done) {
        cudaFuncSetAttribute(mma_gemm_h<true, true, false, true, false>,
                             cudaFuncAttributeMaxDynamicSharedMemorySize, GEMM_SMEM);
        cudaFuncSetAttribute(mma_gemm_h<false, true, true, false, false>,
                             cudaFuncAttributeMaxDynamicSharedMemorySize, GEMM_SMEM);
        cudaFuncSetAttribute(mma_gemm_h<false, false, false, true, true>,
                             cudaFuncAttributeMaxDynamicSharedMemorySize, GEMM_SMEM);
        cudaFuncSetAttribute(attn_mma_kernel,
                             cudaFuncAttributeMaxDynamicSharedMemorySize, ATT_SMEM);
        attr_done = true;
    }

    prep_kernel<<<PREP_W2H_BLOCKS + N_, 256>>>(
        w_qkv, w_pw1, w_pw2, w_proj, wh, rel_index, rel_table, gbias);

    // 1) x1 = x + MLP(LN2(x))
    ln_kernel<<<M_ / 8, 256>>>(x, ln2_g, ln2_b, (__half*)p_ln2);
    mma_gemm_h<true, true, false, true, false><<<dim3(HID_ / 128, M_ / 128), 256, GEMM_SMEM>>>(
        (const __half*)p_ln2, wh + OFF_PW1, b_pw1, nullptr, p_h1, M_, HID_, C_);
    dwconv_kernel<<<dim3(32, B_, 2), 384>>>(
        (const __half*)p_h1, (__half*)p_h2, w_dw, b_dw);
    mma_gemm_h<false, true, true, false, false><<<dim3(C_ / 128, M_ / 128), 256, GEMM_SMEM>>>(
        (const __half*)p_h2, wh + OFF_PW2, b_pw2, x, p_x1, M_, C_, HID_);

    // 2) out = x1 + Attn(LN1(x1))
    ln_kernel<<<M_ / 8, 256>>>((const float*)p_x1, ln1_g, ln1_b, (__half*)p_ln1);
    mma_gemm_h<false, false, false, true, true><<<dim3(1152 / 128, M_ / 128), 256, GEMM_SMEM>>>(
        (const __half*)p_ln1, wh + OFF_QKV, nullptr, nullptr, p_qkvh, M_, 1152, C_);
    attn_mma_kernel<<<dim3(N_ / 128, H_, B_), 256, ATT_SMEM>>>(
        (const __half*)p_qkvh, (__half*)p_atth);
    mma_gemm_h<false, true, true, false, false><<<dim3(C_ / 128, M_ / 128), 256, GEMM_SMEM>>>(
        (const __half*)p_atth, wh + OFF_PROJ, b_proj, (const float*)p_x1, out, M_, C_, C_);
}